// round 2
// baseline (speedup 1.0000x reference)
#include <cuda_runtime.h>
#include <cuda_bf16.h>
#include <math.h>

#define BATCH 2
#define SEQ   2048
#define EMB   1024
#define HEADS 16
#define HDIM  64
#define MTOT  (BATCH*SEQ)      // 4096
#define NQKV  (3*EMB)          // 3072

// ---------------- scratch (no allocation allowed) ----------------
__device__ float g_qkv[(size_t)MTOT*NQKV];   // [B*S, 3E] plain layout (like reference pre-reshape)
__device__ float g_att[(size_t)MTOT*EMB];    // [B,S,E] attention output
__device__ float g_pj [(size_t)MTOT*EMB];    // [B,S,E] proj output (pre-LN)

// ---------------------------------------------------------------------------
// SGEMM (TN): C[m, n] = sum_k A[m,k] * B[n,k] + bias[n]
// A: [M,K] row-major, B: [N,K] row-major, C: row stride ldc.
// Tiles: 128x128x16, 256 threads, 8x8 micro-tile per thread.
// ---------------------------------------------------------------------------
__global__ __launch_bounds__(256)
void sgemm_tn(const float* __restrict__ A, const float* __restrict__ Bm,
              const float* __restrict__ bias, float* __restrict__ C,
              int K, int ldc)
{
    __shared__ float As[16][128];
    __shared__ float Bs[16][128];

    const int tid = threadIdx.x;
    const int tx  = tid & 15;       // n dir
    const int ty  = tid >> 4;       // m dir
    const int m0  = blockIdx.y * 128;
    const int n0  = blockIdx.x * 128;

    float acc[8][8];
#pragma unroll
    for (int i = 0; i < 8; i++)
#pragma unroll
        for (int j = 0; j < 8; j++) acc[i][j] = 0.f;

    for (int k0 = 0; k0 < K; k0 += 16) {
#pragma unroll
        for (int it = 0; it < 2; it++) {
            int v   = tid + it * 256;      // 0..511
            int row = v >> 2;              // 0..127
            int kc  = (v & 3) * 4;         // 0,4,8,12
            float4 a = *(const float4*)&A[(size_t)(m0 + row) * K + k0 + kc];
            As[kc + 0][row] = a.x;  As[kc + 1][row] = a.y;
            As[kc + 2][row] = a.z;  As[kc + 3][row] = a.w;
            float4 b = *(const float4*)&Bm[(size_t)(n0 + row) * K + k0 + kc];
            Bs[kc + 0][row] = b.x;  Bs[kc + 1][row] = b.y;
            Bs[kc + 2][row] = b.z;  Bs[kc + 3][row] = b.w;
        }
        __syncthreads();

#pragma unroll
        for (int k = 0; k < 16; k++) {
            float4 a0 = *(const float4*)&As[k][ty * 8];
            float4 a1 = *(const float4*)&As[k][ty * 8 + 4];
            float4 b0 = *(const float4*)&Bs[k][tx * 8];
            float4 b1 = *(const float4*)&Bs[k][tx * 8 + 4];
            float av[8] = {a0.x, a0.y, a0.z, a0.w, a1.x, a1.y, a1.z, a1.w};
            float bv[8] = {b0.x, b0.y, b0.z, b0.w, b1.x, b1.y, b1.z, b1.w};
#pragma unroll
            for (int i = 0; i < 8; i++)
#pragma unroll
                for (int j = 0; j < 8; j++)
                    acc[i][j] = fmaf(av[i], bv[j], acc[i][j]);
        }
        __syncthreads();
    }

#pragma unroll
    for (int i = 0; i < 8; i++) {
        int m = m0 + ty * 8 + i;
#pragma unroll
        for (int j = 0; j < 8; j++) {
            int n = n0 + tx * 8 + j;
            C[(size_t)m * ldc + n] = acc[i][j] + bias[n];
        }
    }
}

// ---------------------------------------------------------------------------
// Flash attention, fp32, canonical (unguarded) online softmax.
// One query per thread, 128 queries per block. K/V tiles of 64 rows in smem.
// Q/K/V read directly from g_qkv [B*S, 3E] at col offsets h*64 / E+h*64 / 2E+h*64.
// grid: (SEQ/128, HEADS, BATCH)
// ---------------------------------------------------------------------------
__global__ __launch_bounds__(128)
void attn_kernel()
{
    const int t  = threadIdx.x;
    const int h  = blockIdx.y;
    const int b  = blockIdx.z;
    const int qi = blockIdx.x * 128 + t;

    __shared__ float Ks[64 * 64];
    __shared__ float Vs[64 * 64];

    // load q (scaled by 1/sqrt(64) = 0.125)
    float4 q[16];
    {
        const float4* qp = (const float4*)(g_qkv + ((size_t)(b * SEQ + qi)) * NQKV + h * HDIM);
#pragma unroll
        for (int i = 0; i < 16; i++) {
            float4 v = qp[i];
            v.x *= 0.125f; v.y *= 0.125f; v.z *= 0.125f; v.w *= 0.125f;
            q[i] = v;
        }
    }

    float o[64];
#pragma unroll
    for (int i = 0; i < 64; i++) o[i] = 0.f;
    float m = -1e30f, l = 0.f;

    const int c  = t & 15;   // float4 column within a 64-float row
    const int r0 = t >> 4;   // starting row

    for (int j0 = 0; j0 < SEQ; j0 += 64) {
        __syncthreads();
#pragma unroll
        for (int i = 0; i < 8; i++) {
            int r = r0 + 8 * i;                   // 0..63
            size_t rowbase = ((size_t)(b * SEQ + j0 + r)) * NQKV + h * HDIM;
            ((float4*)Ks)[r * 16 + c] = ((const float4*)(g_qkv + rowbase + EMB))[c];
            ((float4*)Vs)[r * 16 + c] = ((const float4*)(g_qkv + rowbase + 2 * EMB))[c];
        }
        __syncthreads();

        for (int j = 0; j < 64; j++) {
            const float4* kr = (const float4*)(Ks + j * 64);
            float s0 = 0.f, s1 = 0.f, s2 = 0.f, s3 = 0.f;
#pragma unroll
            for (int i = 0; i < 16; i++) {
                float4 kv = kr[i];
                s0 = fmaf(q[i].x, kv.x, s0);
                s1 = fmaf(q[i].y, kv.y, s1);
                s2 = fmaf(q[i].z, kv.z, s2);
                s3 = fmaf(q[i].w, kv.w, s3);
            }
            float s = (s0 + s1) + (s2 + s3);

            float m_new = fmaxf(m, s);
            float corr  = __expf(m - m_new);
            float p     = __expf(s - m_new);
            l = l * corr + p;
            m = m_new;

            const float4* vr = (const float4*)(Vs + j * 64);
#pragma unroll
            for (int i = 0; i < 16; i++) {
                float4 vv = vr[i];
                o[4 * i + 0] = fmaf(o[4 * i + 0], corr, p * vv.x);
                o[4 * i + 1] = fmaf(o[4 * i + 1], corr, p * vv.y);
                o[4 * i + 2] = fmaf(o[4 * i + 2], corr, p * vv.z);
                o[4 * i + 3] = fmaf(o[4 * i + 3], corr, p * vv.w);
            }
        }
    }

    float inv = 1.f / l;
    float4* op = (float4*)(g_att + ((size_t)(b * SEQ + qi)) * EMB + h * HDIM);
#pragma unroll
    for (int i = 0; i < 16; i++) {
        float4 v;
        v.x = o[4 * i + 0] * inv;
        v.y = o[4 * i + 1] * inv;
        v.z = o[4 * i + 2] * inv;
        v.w = o[4 * i + 3] * inv;
        op[i] = v;
    }
}

// ---------------------------------------------------------------------------
// Residual + LayerNorm. One block (256 thr) per row; 4 elems/thread.
// ---------------------------------------------------------------------------
__global__ __launch_bounds__(256)
void ln_kernel(const float* __restrict__ x, const float* __restrict__ gamma,
               const float* __restrict__ beta, float* __restrict__ out)
{
    const int row = blockIdx.x;
    const int t   = threadIdx.x;
    const size_t off = (size_t)row * EMB + t * 4;

    float4 a = *(const float4*)&g_pj[off];
    float4 r = *(const float4*)&x[off];
    float y0 = a.x + r.x, y1 = a.y + r.y, y2 = a.z + r.z, y3 = a.w + r.w;

    float s  = (y0 + y1) + (y2 + y3);
    float ss = fmaf(y0, y0, fmaf(y1, y1, fmaf(y2, y2, y3 * y3)));

#pragma unroll
    for (int offx = 16; offx > 0; offx >>= 1) {
        s  += __shfl_xor_sync(0xffffffffu, s,  offx);
        ss += __shfl_xor_sync(0xffffffffu, ss, offx);
    }
    __shared__ float sbuf[8], ssbuf[8];
    int lane = t & 31, w = t >> 5;
    if (lane == 0) { sbuf[w] = s; ssbuf[w] = ss; }
    __syncthreads();
    if (w == 0) {
        float sv  = (lane < 8) ? sbuf[lane]  : 0.f;
        float ssv = (lane < 8) ? ssbuf[lane] : 0.f;
#pragma unroll
        for (int offx = 4; offx > 0; offx >>= 1) {
            sv  += __shfl_xor_sync(0xffffffffu, sv,  offx);
            ssv += __shfl_xor_sync(0xffffffffu, ssv, offx);
        }
        if (lane == 0) { sbuf[0] = sv; ssbuf[0] = ssv; }
    }
    __syncthreads();
    float mu  = sbuf[0] * (1.f / EMB);
    float var = ssbuf[0] * (1.f / EMB) - mu * mu;
    float rs  = rsqrtf(var + 1e-5f);

    float4 g  = *(const float4*)&gamma[t * 4];
    float4 be = *(const float4*)&beta[t * 4];
    float4 ov;
    ov.x = (y0 - mu) * rs * g.x + be.x;
    ov.y = (y1 - mu) * rs * g.y + be.y;
    ov.z = (y2 - mu) * rs * g.z + be.z;
    ov.w = (y3 - mu) * rs * g.w + be.w;
    *(float4*)&out[off] = ov;
}

// ---------------------------------------------------------------------------
extern "C" void kernel_launch(void* const* d_in, const int* in_sizes, int n_in,
                              void* d_out, int out_size)
{
    const float* x      = (const float*)d_in[0];
    const float* W_qkv  = (const float*)d_in[1];
    const float* b_qkv  = (const float*)d_in[2];
    const float* W_proj = (const float*)d_in[3];
    const float* b_proj = (const float*)d_in[4];
    const float* gamma  = (const float*)d_in[5];
    const float* beta   = (const float*)d_in[6];
    float* out = (float*)d_out;

    float* qkv_buf = nullptr;  cudaGetSymbolAddress((void**)&qkv_buf, g_qkv);
    float* att_buf = nullptr;  cudaGetSymbolAddress((void**)&att_buf, g_att);
    float* pj_buf  = nullptr;  cudaGetSymbolAddress((void**)&pj_buf,  g_pj);

    // 1) QKV projection -> [B*S, 3E] plain layout
    sgemm_tn<<<dim3(NQKV / 128, MTOT / 128), 256>>>(x, W_qkv, b_qkv, qkv_buf, EMB, NQKV);
    // 2) attention (reads g_qkv directly)
    attn_kernel<<<dim3(SEQ / 128, HEADS, BATCH), 128>>>();
    // 3) output projection
    sgemm_tn<<<dim3(EMB / 128, MTOT / 128), 256>>>(att_buf, W_proj, b_proj, pj_buf, EMB, EMB);
    // 4) residual + layernorm
    ln_kernel<<<MTOT, 256>>>(x, gamma, beta, out);
}

// round 4
// speedup vs baseline: 1.4619x; 1.4619x over previous
#include <cuda_runtime.h>
#include <cuda_bf16.h>
#include <math.h>
#include <stdint.h>

#define BATCH 2
#define SEQ   2048
#define EMB   1024
#define HEADS 16
#define HDIM  64
#define MTOT  4096
#define NQKV  3072

// ---------------- scratch (no allocation allowed) ----------------
__device__ float g_qkv[(size_t)MTOT*NQKV];       // fp32 QKV, [B*S, 3E]
__device__ float g_att[(size_t)MTOT*EMB];        // fp32 attention out
__device__ float g_pj [(size_t)MTOT*EMB];        // fp32 proj out (pre-LN)
__device__ __nv_bfloat16 g_xb    [(size_t)MTOT*EMB];
__device__ __nv_bfloat16 g_wqkvb [(size_t)NQKV*EMB];
__device__ __nv_bfloat16 g_wprojb[(size_t)EMB*EMB];
__device__ __nv_bfloat16 g_attb  [(size_t)MTOT*EMB];

// ======================= PTX helpers (base-target only) ==================
__device__ __forceinline__ uint32_t smem_u32(const void* p) {
    uint32_t a;
    asm("{ .reg .u64 t; cvta.to.shared.u64 t, %1; cvt.u32.u64 %0, t; }" : "=r"(a) : "l"(p));
    return a;
}
#define CP16(dst, src) asm volatile("cp.async.cg.shared.global [%0], [%1], 16;" :: "r"(dst), "l"(src) : "memory")
#define CPCOMMIT()     asm volatile("cp.async.commit_group;" ::: "memory")
#define CPWAIT1()      asm volatile("cp.async.wait_group 1;" ::: "memory")
#define CPWAIT0()      asm volatile("cp.async.wait_group 0;" ::: "memory")

#define LDSM4(r, addr) \
    asm volatile("ldmatrix.sync.aligned.m8n8.x4.shared.b16 {%0,%1,%2,%3}, [%4];" \
        : "=r"((r)[0]), "=r"((r)[1]), "=r"((r)[2]), "=r"((r)[3]) : "r"(addr))

#define MMA16816(d, a, b0, b1) \
    asm volatile("mma.sync.aligned.m16n8k16.row.col.f32.bf16.bf16.f32 " \
        "{%0,%1,%2,%3}, {%4,%5,%6,%7}, {%8,%9}, {%0,%1,%2,%3};" \
        : "+f"((d)[0]), "+f"((d)[1]), "+f"((d)[2]), "+f"((d)[3]) \
        : "r"((a)[0]), "r"((a)[1]), "r"((a)[2]), "r"((a)[3]), "r"(b0), "r"(b1))

// ======================= mma.sync bf16 GEMM (TN) =========================
// C[m,n] = sum_k A[m,k] * B[n,k] + bias[n]
// 128x128 tile/CTA, 8 warps (2x4), 64x32 per warp, K chunks of 64,
// double-buffered cp.async, padded smem rows (LDA=72 bf16) for ldmatrix.
#define KC       64
#define LDAP     72                       // padded row length in bf16 elems
#define ROWB     (LDAP*2)                 // 144 bytes
#define OPER_B   (128*ROWB)               // 18432 bytes per operand per stage
#define GEMM_SMEM (2*2*OPER_B)            // 73728 bytes

__global__ __launch_bounds__(256)
void gemm_mma(const __nv_bfloat16* __restrict__ A, const __nv_bfloat16* __restrict__ B,
              const float* __restrict__ bias, float* __restrict__ C, int K, int ldc)
{
    extern __shared__ __align__(128) char smem[];
    const uint32_t sb = smem_u32(smem);
    const int tid  = threadIdx.x;
    const int wid  = tid >> 5, lane = tid & 31;
    const int m0   = blockIdx.y * 128, n0 = blockIdx.x * 128;
    const int wm   = (wid >> 2) * 64;       // warp row base within tile
    const int wn   = (wid & 3) * 32;        // warp col base within tile

    float acc[4][4][4];
#pragma unroll
    for (int i = 0; i < 4; i++)
#pragma unroll
        for (int j = 0; j < 4; j++)
#pragma unroll
            for (int c = 0; c < 4; c++) acc[i][j][c] = 0.f;

    const __nv_bfloat16* Ab = A + (size_t)m0 * K;
    const __nv_bfloat16* Bb = B + (size_t)n0 * K;

    auto load_stage = [&](int chunk, int s) {
        uint32_t baseA = sb + s * 2 * OPER_B;
        uint32_t baseB = baseA + OPER_B;
        const __nv_bfloat16* Ag = Ab + chunk * KC;
        const __nv_bfloat16* Bg = Bb + chunk * KC;
#pragma unroll
        for (int u = 0; u < 4; u++) {
            int id  = tid + u * 256;          // 0..1023
            int row = id >> 3, c16 = id & 7;  // 8 x 16B chunks per 128B row
            CP16(baseA + row * ROWB + c16 * 16, Ag + (size_t)row * K + c16 * 8);
            CP16(baseB + row * ROWB + c16 * 16, Bg + (size_t)row * K + c16 * 8);
        }
        CPCOMMIT();
    };

    const int NCH = K / KC;
    load_stage(0, 0);
    for (int i = 0; i < NCH; i++) {
        if (i + 1 < NCH) { load_stage(i + 1, (i + 1) & 1); CPWAIT1(); }
        else             { CPWAIT0(); }
        __syncthreads();

        const uint32_t baseA = sb + (i & 1) * 2 * OPER_B;
        const uint32_t baseB = baseA + OPER_B;
#pragma unroll
        for (int kk = 0; kk < 4; kk++) {           // 4 k-steps of 16
            uint32_t af[4][4], bfr[2][4];
#pragma unroll
            for (int t4 = 0; t4 < 4; t4++) {
                uint32_t addr = baseA + (uint32_t)(wm + t4 * 16 + (lane & 15)) * ROWB
                              + (uint32_t)(kk * 16 + (lane >> 4) * 8) * 2;
                LDSM4(af[t4], addr);
            }
#pragma unroll
            for (int t2 = 0; t2 < 2; t2++) {
                uint32_t addr = baseB + (uint32_t)(wn + t2 * 16 + (lane & 15)) * ROWB
                              + (uint32_t)(kk * 16 + (lane >> 4) * 8) * 2;
                LDSM4(bfr[t2], addr);
            }
#pragma unroll
            for (int mi = 0; mi < 4; mi++)
#pragma unroll
                for (int nj = 0; nj < 4; nj++) {
                    uint32_t b0 = bfr[nj >> 1][nj & 1];
                    uint32_t b1 = bfr[nj >> 1][(nj & 1) + 2];
                    MMA16816(acc[mi][nj], af[mi], b0, b1);
                }
        }
        __syncthreads();
    }

    // epilogue: direct stores + bias (fragment layout: row=lane/4, col=2*(lane%4))
    const int r  = lane >> 2;
    const int cq = (lane & 3) * 2;
#pragma unroll
    for (int mi = 0; mi < 4; mi++) {
        int row0 = m0 + wm + mi * 16 + r;
#pragma unroll
        for (int nj = 0; nj < 4; nj++) {
            int col = n0 + wn + nj * 8 + cq;
            float2 bv = *(const float2*)(bias + col);
            float2 v0, v1;
            v0.x = acc[mi][nj][0] + bv.x;  v0.y = acc[mi][nj][1] + bv.y;
            v1.x = acc[mi][nj][2] + bv.x;  v1.y = acc[mi][nj][3] + bv.y;
            *(float2*)(C + (size_t)row0 * ldc + col)       = v0;
            *(float2*)(C + (size_t)(row0 + 8) * ldc + col) = v1;
        }
    }
}

// ======================= fp32 -> bf16 convert ============================
__global__ __launch_bounds__(256)
void f2bf_kernel(const float* __restrict__ in, __nv_bfloat16* __restrict__ out, int n4)
{
    int i = blockIdx.x * blockDim.x + threadIdx.x;
    if (i >= n4) return;
    float4 v = ((const float4*)in)[i];
    __nv_bfloat162 a = __floats2bfloat162_rn(v.x, v.y);
    __nv_bfloat162 b = __floats2bfloat162_rn(v.z, v.w);
    uint2 pk;
    pk.x = *(uint32_t*)&a; pk.y = *(uint32_t*)&b;
    ((uint2*)out)[i] = pk;
}

// ======================= flash attention (fp32, known-correct) ===========
__global__ __launch_bounds__(128)
void attn_kernel()
{
    const int t  = threadIdx.x;
    const int h  = blockIdx.y;
    const int b  = blockIdx.z;
    const int qi = blockIdx.x * 128 + t;

    __shared__ float Ks[64 * 64];
    __shared__ float Vs[64 * 64];

    float4 q[16];
    {
        const float4* qp = (const float4*)(g_qkv + ((size_t)(b * SEQ + qi)) * NQKV + h * HDIM);
#pragma unroll
        for (int i = 0; i < 16; i++) {
            float4 v = qp[i];
            v.x *= 0.125f; v.y *= 0.125f; v.z *= 0.125f; v.w *= 0.125f;
            q[i] = v;
        }
    }

    float o[64];
#pragma unroll
    for (int i = 0; i < 64; i++) o[i] = 0.f;
    float m = -1e30f, l = 0.f;

    const int c  = t & 15;
    const int r0 = t >> 4;

    for (int j0 = 0; j0 < SEQ; j0 += 64) {
        __syncthreads();
#pragma unroll
        for (int i = 0; i < 8; i++) {
            int r = r0 + 8 * i;
            size_t rowbase = ((size_t)(b * SEQ + j0 + r)) * NQKV + h * HDIM;
            ((float4*)Ks)[r * 16 + c] = ((const float4*)(g_qkv + rowbase + EMB))[c];
            ((float4*)Vs)[r * 16 + c] = ((const float4*)(g_qkv + rowbase + 2 * EMB))[c];
        }
        __syncthreads();

        for (int j = 0; j < 64; j++) {
            const float4* kr = (const float4*)(Ks + j * 64);
            float s0 = 0.f, s1 = 0.f, s2 = 0.f, s3 = 0.f;
#pragma unroll
            for (int i = 0; i < 16; i++) {
                float4 kv = kr[i];
                s0 = fmaf(q[i].x, kv.x, s0);
                s1 = fmaf(q[i].y, kv.y, s1);
                s2 = fmaf(q[i].z, kv.z, s2);
                s3 = fmaf(q[i].w, kv.w, s3);
            }
            float s = (s0 + s1) + (s2 + s3);

            float m_new = fmaxf(m, s);
            float corr  = __expf(m - m_new);
            float p     = __expf(s - m_new);
            l = l * corr + p;
            m = m_new;

            const float4* vr = (const float4*)(Vs + j * 64);
#pragma unroll
            for (int i = 0; i < 16; i++) {
                float4 vv = vr[i];
                o[4 * i + 0] = fmaf(o[4 * i + 0], corr, p * vv.x);
                o[4 * i + 1] = fmaf(o[4 * i + 1], corr, p * vv.y);
                o[4 * i + 2] = fmaf(o[4 * i + 2], corr, p * vv.z);
                o[4 * i + 3] = fmaf(o[4 * i + 3], corr, p * vv.w);
            }
        }
    }

    float inv = 1.f / l;
    float4* op = (float4*)(g_att + ((size_t)(b * SEQ + qi)) * EMB + h * HDIM);
#pragma unroll
    for (int i = 0; i < 16; i++) {
        float4 v;
        v.x = o[4 * i + 0] * inv;
        v.y = o[4 * i + 1] * inv;
        v.z = o[4 * i + 2] * inv;
        v.w = o[4 * i + 3] * inv;
        op[i] = v;
    }
}

// ======================= residual + LayerNorm ============================
__global__ __launch_bounds__(256)
void ln_kernel(const float* __restrict__ x, const float* __restrict__ gamma,
               const float* __restrict__ beta, float* __restrict__ out)
{
    const int row = blockIdx.x;
    const int t   = threadIdx.x;
    const size_t off = (size_t)row * EMB + t * 4;

    float4 a = *(const float4*)&g_pj[off];
    float4 r = *(const float4*)&x[off];
    float y0 = a.x + r.x, y1 = a.y + r.y, y2 = a.z + r.z, y3 = a.w + r.w;

    float s  = (y0 + y1) + (y2 + y3);
    float ss = fmaf(y0, y0, fmaf(y1, y1, fmaf(y2, y2, y3 * y3)));

#pragma unroll
    for (int offx = 16; offx > 0; offx >>= 1) {
        s  += __shfl_xor_sync(0xffffffffu, s,  offx);
        ss += __shfl_xor_sync(0xffffffffu, ss, offx);
    }
    __shared__ float sbuf[8], ssbuf[8];
    int lane = t & 31, w = t >> 5;
    if (lane == 0) { sbuf[w] = s; ssbuf[w] = ss; }
    __syncthreads();
    if (w == 0) {
        float sv  = (lane < 8) ? sbuf[lane]  : 0.f;
        float ssv = (lane < 8) ? ssbuf[lane] : 0.f;
#pragma unroll
        for (int offx = 4; offx > 0; offx >>= 1) {
            sv  += __shfl_xor_sync(0xffffffffu, sv,  offx);
            ssv += __shfl_xor_sync(0xffffffffu, ssv, offx);
        }
        if (lane == 0) { sbuf[0] = sv; ssbuf[0] = ssv; }
    }
    __syncthreads();
    float mu  = sbuf[0] * (1.f / EMB);
    float var = ssbuf[0] * (1.f / EMB) - mu * mu;
    float rs  = rsqrtf(var + 1e-5f);

    float4 g  = *(const float4*)&gamma[t * 4];
    float4 be = *(const float4*)&beta[t * 4];
    float4 ov;
    ov.x = (y0 - mu) * rs * g.x + be.x;
    ov.y = (y1 - mu) * rs * g.y + be.y;
    ov.z = (y2 - mu) * rs * g.z + be.z;
    ov.w = (y3 - mu) * rs * g.w + be.w;
    *(float4*)&out[off] = ov;
}

// =========================================================================
extern "C" void kernel_launch(void* const* d_in, const int* in_sizes, int n_in,
                              void* d_out, int out_size)
{
    const float* x      = (const float*)d_in[0];
    const float* W_qkv  = (const float*)d_in[1];
    const float* b_qkv  = (const float*)d_in[2];
    const float* W_proj = (const float*)d_in[3];
    const float* b_proj = (const float*)d_in[4];
    const float* gamma  = (const float*)d_in[5];
    const float* beta   = (const float*)d_in[6];
    float* out = (float*)d_out;

    float* qkv_buf; cudaGetSymbolAddress((void**)&qkv_buf, g_qkv);
    float* pj_buf;  cudaGetSymbolAddress((void**)&pj_buf,  g_pj);
    float* att_buf; cudaGetSymbolAddress((void**)&att_buf, g_att);
    __nv_bfloat16 *xb, *wqb, *wpb, *atb;
    cudaGetSymbolAddress((void**)&xb,  g_xb);
    cudaGetSymbolAddress((void**)&wqb, g_wqkvb);
    cudaGetSymbolAddress((void**)&wpb, g_wprojb);
    cudaGetSymbolAddress((void**)&atb, g_attb);

    cudaFuncSetAttribute(gemm_mma, cudaFuncAttributeMaxDynamicSharedMemorySize, GEMM_SMEM);

    // bf16 conversions of GEMM inputs
    f2bf_kernel<<<(MTOT * EMB / 4 + 255) / 256, 256>>>(x, xb, MTOT * EMB / 4);
    f2bf_kernel<<<(NQKV * EMB / 4 + 255) / 256, 256>>>(W_qkv, wqb, NQKV * EMB / 4);
    f2bf_kernel<<<(EMB * EMB / 4 + 255) / 256, 256>>>(W_proj, wpb, EMB * EMB / 4);

    // 1) QKV projection (tensor cores via mma.sync)
    gemm_mma<<<dim3(NQKV / 128, MTOT / 128), 256, GEMM_SMEM>>>(xb, wqb, b_qkv, qkv_buf, EMB, NQKV);
    // 2) attention (fp32)
    attn_kernel<<<dim3(SEQ / 128, HEADS, BATCH), 128>>>();
    // 3) attn out -> bf16, then output projection (tensor cores)
    f2bf_kernel<<<(MTOT * EMB / 4 + 255) / 256, 256>>>(att_buf, atb, MTOT * EMB / 4);
    gemm_mma<<<dim3(EMB / 128, MTOT / 128), 256, GEMM_SMEM>>>(atb, wpb, b_proj, pj_buf, EMB, EMB);
    // 4) residual + layernorm
    ln_kernel<<<MTOT, 256>>>(x, gamma, beta, out);
}

// round 5
// speedup vs baseline: 8.1365x; 5.5657x over previous
#include <cuda_runtime.h>
#include <cuda_bf16.h>
#include <math.h>
#include <stdint.h>

#define BATCH 2
#define SEQ   2048
#define EMB   1024
#define HEADS 16
#define HDIM  64
#define MTOT  4096
#define NQKV  3072

// ---------------- scratch (no allocation allowed) ----------------
__device__ __nv_bfloat16 g_qkvb [(size_t)MTOT*NQKV];  // bf16 QKV [B*S, 3E]
__device__ __nv_bfloat16 g_attb [(size_t)MTOT*EMB];   // bf16 attention out
__device__ float         g_pj   [(size_t)MTOT*EMB];   // fp32 proj out (pre-LN)
__device__ __nv_bfloat16 g_xb   [(size_t)MTOT*EMB];
__device__ __nv_bfloat16 g_wqkvb[(size_t)NQKV*EMB];
__device__ __nv_bfloat16 g_wprojb[(size_t)EMB*EMB];

// ======================= PTX helpers (base-target only) ==================
__device__ __forceinline__ uint32_t smem_u32(const void* p) {
    uint32_t a;
    asm("{ .reg .u64 t; cvta.to.shared.u64 t, %1; cvt.u32.u64 %0, t; }" : "=r"(a) : "l"(p));
    return a;
}
#define CP16(dst, src) asm volatile("cp.async.cg.shared.global [%0], [%1], 16;" :: "r"(dst), "l"(src) : "memory")
#define CPCOMMIT()     asm volatile("cp.async.commit_group;" ::: "memory")
#define CPWAIT1()      asm volatile("cp.async.wait_group 1;" ::: "memory")
#define CPWAIT0()      asm volatile("cp.async.wait_group 0;" ::: "memory")

#define LDSM4(r, addr) \
    asm volatile("ldmatrix.sync.aligned.m8n8.x4.shared.b16 {%0,%1,%2,%3}, [%4];" \
        : "=r"((r)[0]), "=r"((r)[1]), "=r"((r)[2]), "=r"((r)[3]) : "r"(addr))
#define LDSM4T(r, addr) \
    asm volatile("ldmatrix.sync.aligned.m8n8.x4.trans.shared.b16 {%0,%1,%2,%3}, [%4];" \
        : "=r"((r)[0]), "=r"((r)[1]), "=r"((r)[2]), "=r"((r)[3]) : "r"(addr))

#define MMA16816(d, a, b0, b1) \
    asm volatile("mma.sync.aligned.m16n8k16.row.col.f32.bf16.bf16.f32 " \
        "{%0,%1,%2,%3}, {%4,%5,%6,%7}, {%8,%9}, {%0,%1,%2,%3};" \
        : "+f"((d)[0]), "+f"((d)[1]), "+f"((d)[2]), "+f"((d)[3]) \
        : "r"((a)[0]), "r"((a)[1]), "r"((a)[2]), "r"((a)[3]), "r"(b0), "r"(b1))

__device__ __forceinline__ uint32_t pack_bf16(float a, float b) {
    __nv_bfloat162 v = __floats2bfloat162_rn(a, b);
    return *(uint32_t*)&v;
}

// ======================= mma.sync bf16 GEMM (TN) =========================
// C[m,n] = sum_k A[m,k]*B[n,k] + bias[n];  out fp32 or bf16 (template).
#define KC       64
#define LDAP     72
#define ROWB     (LDAP*2)                 // 144 B
#define OPER_B   (128*ROWB)               // 18432 B per operand per stage
#define GEMM_SMEM (2*2*OPER_B)            // 73728 B

template<bool BF16OUT>
__global__ __launch_bounds__(256)
void gemm_mma(const __nv_bfloat16* __restrict__ A, const __nv_bfloat16* __restrict__ B,
              const float* __restrict__ bias, void* __restrict__ Cv, int K, int ldc)
{
    extern __shared__ __align__(128) char smem[];
    const uint32_t sb = smem_u32(smem);
    const int tid  = threadIdx.x;
    const int wid  = tid >> 5, lane = tid & 31;
    const int m0   = blockIdx.y * 128, n0 = blockIdx.x * 128;
    const int wm   = (wid >> 2) * 64;
    const int wn   = (wid & 3) * 32;

    float acc[4][4][4];
#pragma unroll
    for (int i = 0; i < 4; i++)
#pragma unroll
        for (int j = 0; j < 4; j++)
#pragma unroll
            for (int c = 0; c < 4; c++) acc[i][j][c] = 0.f;

    const __nv_bfloat16* Ab = A + (size_t)m0 * K;
    const __nv_bfloat16* Bb = B + (size_t)n0 * K;

    auto load_stage = [&](int chunk, int s) {
        uint32_t baseA = sb + s * 2 * OPER_B;
        uint32_t baseB = baseA + OPER_B;
        const __nv_bfloat16* Ag = Ab + chunk * KC;
        const __nv_bfloat16* Bg = Bb + chunk * KC;
#pragma unroll
        for (int u = 0; u < 4; u++) {
            int id  = tid + u * 256;
            int row = id >> 3, c16 = id & 7;
            CP16(baseA + row * ROWB + c16 * 16, Ag + (size_t)row * K + c16 * 8);
            CP16(baseB + row * ROWB + c16 * 16, Bg + (size_t)row * K + c16 * 8);
        }
        CPCOMMIT();
    };

    const int NCH = K / KC;
    load_stage(0, 0);
    for (int i = 0; i < NCH; i++) {
        if (i + 1 < NCH) { load_stage(i + 1, (i + 1) & 1); CPWAIT1(); }
        else             { CPWAIT0(); }
        __syncthreads();

        const uint32_t baseA = sb + (i & 1) * 2 * OPER_B;
        const uint32_t baseB = baseA + OPER_B;
#pragma unroll
        for (int kk = 0; kk < 4; kk++) {
            uint32_t af[4][4], bfr[2][4];
#pragma unroll
            for (int t4 = 0; t4 < 4; t4++) {
                uint32_t addr = baseA + (uint32_t)(wm + t4 * 16 + (lane & 15)) * ROWB
                              + (uint32_t)(kk * 16 + (lane >> 4) * 8) * 2;
                LDSM4(af[t4], addr);
            }
#pragma unroll
            for (int t2 = 0; t2 < 2; t2++) {
                uint32_t addr = baseB + (uint32_t)(wn + t2 * 16 + (lane & 15)) * ROWB
                              + (uint32_t)(kk * 16 + (lane >> 4) * 8) * 2;
                LDSM4(bfr[t2], addr);
            }
#pragma unroll
            for (int mi = 0; mi < 4; mi++)
#pragma unroll
                for (int nj = 0; nj < 4; nj++) {
                    uint32_t b0 = bfr[nj >> 1][nj & 1];
                    uint32_t b1 = bfr[nj >> 1][(nj & 1) + 2];
                    MMA16816(acc[mi][nj], af[mi], b0, b1);
                }
        }
        __syncthreads();
    }

    const int r  = lane >> 2;
    const int cq = (lane & 3) * 2;
#pragma unroll
    for (int mi = 0; mi < 4; mi++) {
        int row0 = m0 + wm + mi * 16 + r;
#pragma unroll
        for (int nj = 0; nj < 4; nj++) {
            int col = n0 + wn + nj * 8 + cq;
            float2 bv = *(const float2*)(bias + col);
            float a0 = acc[mi][nj][0] + bv.x, a1 = acc[mi][nj][1] + bv.y;
            float a2 = acc[mi][nj][2] + bv.x, a3 = acc[mi][nj][3] + bv.y;
            if (BF16OUT) {
                __nv_bfloat16* C = (__nv_bfloat16*)Cv;
                *(uint32_t*)(C + (size_t)row0 * ldc + col)       = pack_bf16(a0, a1);
                *(uint32_t*)(C + (size_t)(row0 + 8) * ldc + col) = pack_bf16(a2, a3);
            } else {
                float* C = (float*)Cv;
                *(float2*)(C + (size_t)row0 * ldc + col)       = make_float2(a0, a1);
                *(float2*)(C + (size_t)(row0 + 8) * ldc + col) = make_float2(a2, a3);
            }
        }
    }
}

// ======================= fp32 -> bf16 convert ============================
__global__ __launch_bounds__(256)
void f2bf_kernel(const float* __restrict__ in, __nv_bfloat16* __restrict__ out, int n4)
{
    int i = blockIdx.x * blockDim.x + threadIdx.x;
    if (i >= n4) return;
    float4 v = ((const float4*)in)[i];
    uint2 pk;
    pk.x = pack_bf16(v.x, v.y);
    pk.y = pack_bf16(v.z, v.w);
    ((uint2*)out)[i] = pk;
}

// ======================= mma.sync flash attention ========================
// 256 threads / 8 warps. 128 q-rows per CTA (16 per warp). K/V tiles of 64,
// double-buffered cp.async. S=Q*K^T (TN, non-trans ldmatrix); P kept in regs
// (acc->A fragment identity); O=P*V via ldmatrix.trans on V [key][hd].
#define AT_QS   0
#define AT_KS   18432
#define AT_VS   36864
#define AT_SMEM 55296
#define KVROW   144          // padded row bytes (72 bf16)
#define KVTILE  9216         // 64 * 144

__global__ __launch_bounds__(256)
void attn_mma()
{
    extern __shared__ __align__(128) char smem[];
    const uint32_t sb = smem_u32(smem);
    const int tid = threadIdx.x, wid = tid >> 5, lane = tid & 31;
    const int q0 = blockIdx.x * 128, h = blockIdx.y, bb = blockIdx.z;

    const uint32_t QS = sb + AT_QS;
    const uint32_t KS = sb + AT_KS;
    const uint32_t VS = sb + AT_VS;

    // ---- Q tile (128 x 64 bf16) ----
    {
        const __nv_bfloat16* gq = g_qkvb + ((size_t)(bb * SEQ + q0)) * NQKV + h * HDIM;
#pragma unroll
        for (int u = 0; u < 4; u++) {
            int id = tid + u * 256;
            int row = id >> 3, ch = id & 7;
            CP16(QS + row * KVROW + ch * 16, gq + (size_t)row * NQKV + ch * 8);
        }
        CPCOMMIT();
    }
    auto load_kv = [&](int kt, int s) {
        const __nv_bfloat16* gk = g_qkvb + ((size_t)(bb * SEQ + kt * 64)) * NQKV + EMB + h * HDIM;
        const __nv_bfloat16* gv = gk + EMB;
        uint32_t kd = KS + s * KVTILE, vd = VS + s * KVTILE;
#pragma unroll
        for (int u = 0; u < 2; u++) {
            int id = tid + u * 256;           // 0..511
            int row = id >> 3, ch = id & 7;
            CP16(kd + row * KVROW + ch * 16, gk + (size_t)row * NQKV + ch * 8);
            CP16(vd + row * KVROW + ch * 16, gv + (size_t)row * NQKV + ch * 8);
        }
        CPCOMMIT();
    };
    load_kv(0, 0);

    CPWAIT1();            // Q group done (KV0 may be pending)
    __syncthreads();

    // ---- Q fragments (held all kernel), scaled by 1/sqrt(64) ----
    uint32_t qf[4][4];
#pragma unroll
    for (int t = 0; t < 4; t++) {
        uint32_t addr = QS + (uint32_t)(wid * 16 + (lane & 15)) * KVROW
                      + (uint32_t)(t * 16 + (lane >> 4) * 8) * 2;
        LDSM4(qf[t], addr);
    }
    const __nv_bfloat162 qsc = __floats2bfloat162_rn(0.125f, 0.125f);
#pragma unroll
    for (int t = 0; t < 4; t++)
#pragma unroll
        for (int i = 0; i < 4; i++) {
            __nv_bfloat162 v = *(__nv_bfloat162*)&qf[t][i];
            v = __hmul2(v, qsc);
            qf[t][i] = *(uint32_t*)&v;
        }

    float oa[8][4];
#pragma unroll
    for (int j = 0; j < 8; j++)
#pragma unroll
        for (int c = 0; c < 4; c++) oa[j][c] = 0.f;
    float m0 = -1e30f, m1 = -1e30f, l0 = 0.f, l1 = 0.f;

    for (int kt = 0; kt < SEQ / 64; kt++) {
        if (kt + 1 < SEQ / 64) { load_kv(kt + 1, (kt + 1) & 1); CPWAIT1(); }
        else                   { CPWAIT0(); }
        __syncthreads();
        const uint32_t Kst = KS + (kt & 1) * KVTILE;
        const uint32_t Vst = VS + (kt & 1) * KVTILE;

        // ---- S = Q * K^T  (8 n-tiles of 8 keys) ----
        float sacc[8][4];
#pragma unroll
        for (int j = 0; j < 8; j++)
#pragma unroll
            for (int c = 0; c < 4; c++) sacc[j][c] = 0.f;
#pragma unroll
        for (int kk = 0; kk < 4; kk++) {
#pragma unroll
            for (int kg = 0; kg < 4; kg++) {
                uint32_t kf[4];
                uint32_t addr = Kst + (uint32_t)(kg * 16 + (lane & 15)) * KVROW
                              + (uint32_t)(kk * 16 + (lane >> 4) * 8) * 2;
                LDSM4(kf, addr);
                MMA16816(sacc[2 * kg],     qf[kk], kf[0], kf[2]);
                MMA16816(sacc[2 * kg + 1], qf[kk], kf[1], kf[3]);
            }
        }

        // ---- online softmax (rows r=lane/4 and r+8) ----
        float mx0 = -1e30f, mx1 = -1e30f;
#pragma unroll
        for (int j = 0; j < 8; j++) {
            mx0 = fmaxf(mx0, fmaxf(sacc[j][0], sacc[j][1]));
            mx1 = fmaxf(mx1, fmaxf(sacc[j][2], sacc[j][3]));
        }
        mx0 = fmaxf(mx0, __shfl_xor_sync(0xffffffffu, mx0, 1));
        mx0 = fmaxf(mx0, __shfl_xor_sync(0xffffffffu, mx0, 2));
        mx1 = fmaxf(mx1, __shfl_xor_sync(0xffffffffu, mx1, 1));
        mx1 = fmaxf(mx1, __shfl_xor_sync(0xffffffffu, mx1, 2));
        float nm0 = fmaxf(m0, mx0), nm1 = fmaxf(m1, mx1);
        float corr0 = __expf(m0 - nm0), corr1 = __expf(m1 - nm1);
        m0 = nm0; m1 = nm1;

        float rs0 = 0.f, rs1 = 0.f;
#pragma unroll
        for (int j = 0; j < 8; j++) {
            sacc[j][0] = __expf(sacc[j][0] - nm0); rs0 += sacc[j][0];
            sacc[j][1] = __expf(sacc[j][1] - nm0); rs0 += sacc[j][1];
            sacc[j][2] = __expf(sacc[j][2] - nm1); rs1 += sacc[j][2];
            sacc[j][3] = __expf(sacc[j][3] - nm1); rs1 += sacc[j][3];
        }
        rs0 += __shfl_xor_sync(0xffffffffu, rs0, 1);
        rs0 += __shfl_xor_sync(0xffffffffu, rs0, 2);
        rs1 += __shfl_xor_sync(0xffffffffu, rs1, 1);
        rs1 += __shfl_xor_sync(0xffffffffu, rs1, 2);
        l0 = l0 * corr0 + rs0;
        l1 = l1 * corr1 + rs1;
#pragma unroll
        for (int j = 0; j < 8; j++) {
            oa[j][0] *= corr0; oa[j][1] *= corr0;
            oa[j][2] *= corr1; oa[j][3] *= corr1;
        }

        // ---- P -> bf16 A fragments (acc layout == A layout) ----
        uint32_t pf[4][4];
#pragma unroll
        for (int t = 0; t < 4; t++) {
            pf[t][0] = pack_bf16(sacc[2 * t][0],     sacc[2 * t][1]);
            pf[t][1] = pack_bf16(sacc[2 * t][2],     sacc[2 * t][3]);
            pf[t][2] = pack_bf16(sacc[2 * t + 1][0], sacc[2 * t + 1][1]);
            pf[t][3] = pack_bf16(sacc[2 * t + 1][2], sacc[2 * t + 1][3]);
        }

        // ---- O += P * V  (V via ldmatrix.trans: B = V^T) ----
        const int t4 = lane >> 3, lr = lane & 7;
#pragma unroll
        for (int t = 0; t < 4; t++) {
#pragma unroll
            for (int hg = 0; hg < 4; hg++) {
                uint32_t vf[4];
                int key = t * 16 + ((t4 & 1) << 3) + lr;
                int hd  = hg * 16 + ((t4 >> 1) << 3);
                uint32_t addr = Vst + (uint32_t)key * KVROW + (uint32_t)hd * 2;
                LDSM4T(vf, addr);
                MMA16816(oa[2 * hg],     pf[t], vf[0], vf[1]);
                MMA16816(oa[2 * hg + 1], pf[t], vf[2], vf[3]);
            }
        }
        __syncthreads();
    }

    // ---- epilogue: normalize, write bf16 to g_attb ----
    const float inv0 = 1.f / l0, inv1 = 1.f / l1;
    const int r = lane >> 2, cq = (lane & 3) * 2;
    const size_t row0 = (size_t)(bb * SEQ + q0 + wid * 16 + r);
#pragma unroll
    for (int jh = 0; jh < 8; jh++) {
        int col = h * HDIM + jh * 8 + cq;
        *(uint32_t*)(g_attb + row0 * EMB + col) =
            pack_bf16(oa[jh][0] * inv0, oa[jh][1] * inv0);
        *(uint32_t*)(g_attb + (row0 + 8) * EMB + col) =
            pack_bf16(oa[jh][2] * inv1, oa[jh][3] * inv1);
    }
}

// ======================= residual + LayerNorm ============================
__global__ __launch_bounds__(256)
void ln_kernel(const float* __restrict__ x, const float* __restrict__ gamma,
               const float* __restrict__ beta, float* __restrict__ out)
{
    const int row = blockIdx.x;
    const int t   = threadIdx.x;
    const size_t off = (size_t)row * EMB + t * 4;

    float4 a = *(const float4*)&g_pj[off];
    float4 r = *(const float4*)&x[off];
    float y0 = a.x + r.x, y1 = a.y + r.y, y2 = a.z + r.z, y3 = a.w + r.w;

    float s  = (y0 + y1) + (y2 + y3);
    float ss = fmaf(y0, y0, fmaf(y1, y1, fmaf(y2, y2, y3 * y3)));

#pragma unroll
    for (int offx = 16; offx > 0; offx >>= 1) {
        s  += __shfl_xor_sync(0xffffffffu, s,  offx);
        ss += __shfl_xor_sync(0xffffffffu, ss, offx);
    }
    __shared__ float sbuf[8], ssbuf[8];
    int lane = t & 31, w = t >> 5;
    if (lane == 0) { sbuf[w] = s; ssbuf[w] = ss; }
    __syncthreads();
    if (w == 0) {
        float sv  = (lane < 8) ? sbuf[lane]  : 0.f;
        float ssv = (lane < 8) ? ssbuf[lane] : 0.f;
#pragma unroll
        for (int offx = 4; offx > 0; offx >>= 1) {
            sv  += __shfl_xor_sync(0xffffffffu, sv,  offx);
            ssv += __shfl_xor_sync(0xffffffffu, ssv, offx);
        }
        if (lane == 0) { sbuf[0] = sv; ssbuf[0] = ssv; }
    }
    __syncthreads();
    float mu  = sbuf[0] * (1.f / EMB);
    float var = ssbuf[0] * (1.f / EMB) - mu * mu;
    float rs  = rsqrtf(var + 1e-5f);

    float4 g  = *(const float4*)&gamma[t * 4];
    float4 be = *(const float4*)&beta[t * 4];
    float4 ov;
    ov.x = (y0 - mu) * rs * g.x + be.x;
    ov.y = (y1 - mu) * rs * g.y + be.y;
    ov.z = (y2 - mu) * rs * g.z + be.z;
    ov.w = (y3 - mu) * rs * g.w + be.w;
    *(float4*)&out[off] = ov;
}

// =========================================================================
extern "C" void kernel_launch(void* const* d_in, const int* in_sizes, int n_in,
                              void* d_out, int out_size)
{
    const float* x      = (const float*)d_in[0];
    const float* W_qkv  = (const float*)d_in[1];
    const float* b_qkv  = (const float*)d_in[2];
    const float* W_proj = (const float*)d_in[3];
    const float* b_proj = (const float*)d_in[4];
    const float* gamma  = (const float*)d_in[5];
    const float* beta   = (const float*)d_in[6];
    float* out = (float*)d_out;

    float* pj_buf;  cudaGetSymbolAddress((void**)&pj_buf,  g_pj);
    __nv_bfloat16 *xb, *wqb, *wpb, *qkvb, *attb;
    cudaGetSymbolAddress((void**)&xb,   g_xb);
    cudaGetSymbolAddress((void**)&wqb,  g_wqkvb);
    cudaGetSymbolAddress((void**)&wpb,  g_wprojb);
    cudaGetSymbolAddress((void**)&qkvb, g_qkvb);
    cudaGetSymbolAddress((void**)&attb, g_attb);

    cudaFuncSetAttribute(gemm_mma<true>,  cudaFuncAttributeMaxDynamicSharedMemorySize, GEMM_SMEM);
    cudaFuncSetAttribute(gemm_mma<false>, cudaFuncAttributeMaxDynamicSharedMemorySize, GEMM_SMEM);
    cudaFuncSetAttribute(attn_mma,        cudaFuncAttributeMaxDynamicSharedMemorySize, AT_SMEM);

    // bf16 conversions of GEMM inputs
    f2bf_kernel<<<(MTOT * EMB / 4 + 255) / 256, 256>>>(x, xb, MTOT * EMB / 4);
    f2bf_kernel<<<(NQKV * EMB / 4 + 255) / 256, 256>>>(W_qkv, wqb, NQKV * EMB / 4);
    f2bf_kernel<<<(EMB * EMB / 4 + 255) / 256, 256>>>(W_proj, wpb, EMB * EMB / 4);

    // 1) QKV projection -> bf16 QKV
    gemm_mma<true><<<dim3(NQKV / 128, MTOT / 128), 256, GEMM_SMEM>>>(xb, wqb, b_qkv, qkvb, EMB, NQKV);
    // 2) flash attention (tensor cores) -> bf16 attn out
    attn_mma<<<dim3(SEQ / 128, HEADS, BATCH), 256, AT_SMEM>>>();
    // 3) output projection -> fp32
    gemm_mma<false><<<dim3(EMB / 128, MTOT / 128), 256, GEMM_SMEM>>>(attb, wpb, b_proj, pj_buf, EMB, EMB);
    // 4) residual + layernorm
    ln_kernel<<<MTOT, 256>>>(x, gamma, beta, out);
}

// round 6
// speedup vs baseline: 9.0453x; 1.1117x over previous
#include <cuda_runtime.h>
#include <cuda_bf16.h>
#include <math.h>
#include <stdint.h>

#define BATCH 2
#define SEQ   2048
#define EMB   1024
#define HEADS 16
#define HDIM  64
#define MTOT  4096
#define NQKV  3072

// ---------------- scratch (no allocation allowed) ----------------
__device__ __nv_bfloat16 g_qkvb[(size_t)MTOT*NQKV];   // bf16 QKV [B*S, 3E] (row-major)
__device__ float         g_pj  [(size_t)MTOT*EMB];    // fp32 proj out (pre-LN)
// reordered operands: [block128][kchunk64][row 0..127][(c16 ^ (row&7)) * 16B]
__device__ __nv_bfloat16 g_xr  [(size_t)MTOT*EMB];    // x reordered (A of QKV gemm)
__device__ __nv_bfloat16 g_wqr [(size_t)NQKV*EMB];    // W_qkv reordered (B)
__device__ __nv_bfloat16 g_wpr [(size_t)EMB*EMB];     // W_proj reordered (B)
__device__ __nv_bfloat16 g_attr[(size_t)MTOT*EMB];    // attn out, reordered (A of proj gemm)

// ======================= PTX helpers (base-target only) ==================
__device__ __forceinline__ uint32_t smem_u32(const void* p) {
    uint32_t a;
    asm("{ .reg .u64 t; cvta.to.shared.u64 t, %1; cvt.u32.u64 %0, t; }" : "=r"(a) : "l"(p));
    return a;
}
#define CP16(dst, src) asm volatile("cp.async.cg.shared.global [%0], [%1], 16;" :: "r"(dst), "l"(src) : "memory")
#define CPCOMMIT()     asm volatile("cp.async.commit_group;" ::: "memory")
#define CPWAIT1()      asm volatile("cp.async.wait_group 1;" ::: "memory")
#define CPWAIT0()      asm volatile("cp.async.wait_group 0;" ::: "memory")

#define MBAR_INIT(a, c) asm volatile("mbarrier.init.shared.b64 [%0], %1;" :: "r"(a), "r"(c) : "memory")
#define MBAR_ARRIVE(a)  asm volatile("mbarrier.arrive.shared.b64 _, [%0];" :: "r"(a) : "memory")
#define MBAR_EXPECT(a, n) asm volatile("mbarrier.arrive.expect_tx.shared.b64 _, [%0], %1;" :: "r"(a), "r"(n) : "memory")
#define MBAR_WAIT(a, ph) do {                                                        \
    uint32_t _m = (a); uint32_t _p = (ph); uint32_t _d;                              \
    asm volatile("{ .reg .pred p; mbarrier.try_wait.parity.acquire.cta.shared::cta.b64 p, [%1], %2; selp.b32 %0,1,0,p; }" \
        : "=r"(_d) : "r"(_m), "r"(_p) : "memory");                                   \
    if (!_d) {                                                                       \
        asm volatile("{ .reg .pred P1; WL_%=: mbarrier.try_wait.parity.acquire.cta.shared::cta.b64 P1, [%0], %1, 0x989680; @P1 bra.uni WD_%=; bra.uni WL_%=; WD_%=: }" \
            :: "r"(_m), "r"(_p) : "memory");                                         \
    } } while (0)

#define BULKCP(dst, src, bytes, mbar) \
    asm volatile("cp.async.bulk.shared::cta.global.mbarrier::complete_tx::bytes [%0], [%1], %2, [%3];" \
        :: "r"(dst), "l"(src), "r"(bytes), "r"(mbar) : "memory")

#define LDSM4(r, addr) \
    asm volatile("ldmatrix.sync.aligned.m8n8.x4.shared.b16 {%0,%1,%2,%3}, [%4];" \
        : "=r"((r)[0]), "=r"((r)[1]), "=r"((r)[2]), "=r"((r)[3]) : "r"(addr))
#define LDSM4T(r, addr) \
    asm volatile("ldmatrix.sync.aligned.m8n8.x4.trans.shared.b16 {%0,%1,%2,%3}, [%4];" \
        : "=r"((r)[0]), "=r"((r)[1]), "=r"((r)[2]), "=r"((r)[3]) : "r"(addr))

#define MMA16816(d, a, b0, b1) \
    asm volatile("mma.sync.aligned.m16n8k16.row.col.f32.bf16.bf16.f32 " \
        "{%0,%1,%2,%3}, {%4,%5,%6,%7}, {%8,%9}, {%0,%1,%2,%3};" \
        : "+f"((d)[0]), "+f"((d)[1]), "+f"((d)[2]), "+f"((d)[3]) \
        : "r"((a)[0]), "r"((a)[1]), "r"((a)[2]), "r"((a)[3]), "r"(b0), "r"(b1))

__device__ __forceinline__ uint32_t pack_bf16(float a, float b) {
    __nv_bfloat162 v = __floats2bfloat162_rn(a, b);
    return *(uint32_t*)&v;
}

// byte offset into a reordered [R,1024] bf16 matrix for element (row, col)
__device__ __forceinline__ size_t reord_off(int row, int col) {
    int mb = row >> 7, r = row & 127;
    int ch = col >> 6, c16 = (col >> 3) & 7, rem = col & 7;
    return (((size_t)mb * 16 + ch) << 14) + ((size_t)r << 7)
         + ((size_t)(c16 ^ (r & 7)) << 4) + rem * 2;
}

// ======================= reorder: fp32 [R,1024] -> reordered bf16 ========
__global__ __launch_bounds__(256)
void reord_kernel(const float* __restrict__ in, uint4* __restrict__ out, int nunits)
{
    int u = blockIdx.x * 256 + threadIdx.x;
    if (u >= nunits) return;
    int row = u >> 7;               // 128 16B-units per 1024-col row
    int cu  = u & 127;
    int ch  = cu >> 3, c16 = cu & 7;
    const float4* src = (const float4*)(in + (size_t)row * 1024 + cu * 8);
    float4 a = src[0], b = src[1];
    uint4 o;
    o.x = pack_bf16(a.x, a.y);  o.y = pack_bf16(a.z, a.w);
    o.z = pack_bf16(b.x, b.y);  o.w = pack_bf16(b.z, b.w);
    int r = row & 127;
    size_t dst = ((size_t)(row >> 7) * 16 + ch) * 1024 + (size_t)r * 8 + (c16 ^ (r & 7));
    out[dst] = o;
}

// ======================= bulk-copy mma.sync GEMM (TN) ====================
// A, B pre-reordered bf16 ([block][chunk][swizzled 16KB]). K multiple of 64.
// 3-stage cp.async.bulk pipeline, mbarrier ring, no mainloop syncthreads.
#define GSTG   32768                       // A slab 16KB + B slab 16KB
#define GEMM_SMEM (1024 + 3*GSTG)          // 99328

template<bool BF16OUT>
__global__ __launch_bounds__(256)
void gemm_bulk(const __nv_bfloat16* __restrict__ A, const __nv_bfloat16* __restrict__ B,
               const float* __restrict__ bias, void* __restrict__ Cv, int K, int ldc)
{
    extern __shared__ __align__(1024) char smem[];
    const uint32_t sb = smem_u32(smem);
    const int tid  = threadIdx.x;
    const int wid  = tid >> 5, lane = tid & 31;
    const int m0   = blockIdx.y * 128, n0 = blockIdx.x * 128;
    const int wm   = (wid >> 2) * 64;
    const int wn   = (wid & 3) * 32;
    const int NCH  = K >> 6;

    const uint32_t full0  = sb;           // 3 x 8B
    const uint32_t empty0 = sb + 24;      // 3 x 8B

    if (tid == 0) {
#pragma unroll
        for (int s = 0; s < 3; s++) { MBAR_INIT(full0 + s * 8, 1); MBAR_INIT(empty0 + s * 8, 8); }
    }
    __syncthreads();

    const char* Ablk = (const char*)A + ((size_t)blockIdx.y * NCH) * 16384;
    const char* Bblk = (const char*)B + ((size_t)blockIdx.x * NCH) * 16384;

    if (tid == 0) {
#pragma unroll
        for (int c = 0; c < 3; c++) {
            MBAR_EXPECT(full0 + c * 8, 32768u);
            uint32_t st = sb + 1024 + c * GSTG;
            BULKCP(st,         Ablk + (size_t)c * 16384, 16384u, full0 + c * 8);
            BULKCP(st + 16384, Bblk + (size_t)c * 16384, 16384u, full0 + c * 8);
        }
    }

    float acc[4][4][4];
#pragma unroll
    for (int i = 0; i < 4; i++)
#pragma unroll
        for (int j = 0; j < 4; j++)
#pragma unroll
            for (int c = 0; c < 4; c++) acc[i][j][c] = 0.f;

    for (int i = 0; i < NCH; i++) {
        const int s = i % 3;
        MBAR_WAIT(full0 + s * 8, (uint32_t)((i / 3) & 1));
        const uint32_t bA = sb + 1024 + s * GSTG;
        const uint32_t bB = bA + 16384;
#pragma unroll
        for (int kk = 0; kk < 4; kk++) {
            uint32_t af[4][4], bfr[2][4];
            const int c16 = kk * 2 + (lane >> 4);
#pragma unroll
            for (int t4 = 0; t4 < 4; t4++) {
                int rr = wm + t4 * 16 + (lane & 15);
                LDSM4(af[t4], bA + (uint32_t)(rr * 128) + (uint32_t)((c16 ^ (rr & 7)) << 4));
            }
#pragma unroll
            for (int t2 = 0; t2 < 2; t2++) {
                int rr = wn + t2 * 16 + (lane & 15);
                LDSM4(bfr[t2], bB + (uint32_t)(rr * 128) + (uint32_t)((c16 ^ (rr & 7)) << 4));
            }
#pragma unroll
            for (int mi = 0; mi < 4; mi++)
#pragma unroll
                for (int nj = 0; nj < 4; nj++) {
                    uint32_t b0 = bfr[nj >> 1][nj & 1];
                    uint32_t b1 = bfr[nj >> 1][(nj & 1) + 2];
                    MMA16816(acc[mi][nj], af[mi], b0, b1);
                }
        }
        if (lane == 0) MBAR_ARRIVE(empty0 + s * 8);
        if (tid == 0 && i + 3 < NCH) {
            const int j = i + 3;
            const int sj = j % 3;
            MBAR_WAIT(empty0 + sj * 8, (uint32_t)((j / 3 - 1) & 1));
            MBAR_EXPECT(full0 + sj * 8, 32768u);
            uint32_t st = sb + 1024 + sj * GSTG;
            BULKCP(st,         Ablk + (size_t)j * 16384, 16384u, full0 + sj * 8);
            BULKCP(st + 16384, Bblk + (size_t)j * 16384, 16384u, full0 + sj * 8);
        }
    }

    const int r  = lane >> 2;
    const int cq = (lane & 3) * 2;
#pragma unroll
    for (int mi = 0; mi < 4; mi++) {
        int row0 = m0 + wm + mi * 16 + r;
#pragma unroll
        for (int nj = 0; nj < 4; nj++) {
            int col = n0 + wn + nj * 8 + cq;
            float2 bv = *(const float2*)(bias + col);
            float a0 = acc[mi][nj][0] + bv.x, a1 = acc[mi][nj][1] + bv.y;
            float a2 = acc[mi][nj][2] + bv.x, a3 = acc[mi][nj][3] + bv.y;
            if (BF16OUT) {
                __nv_bfloat16* C = (__nv_bfloat16*)Cv;
                *(uint32_t*)(C + (size_t)row0 * ldc + col)       = pack_bf16(a0, a1);
                *(uint32_t*)(C + (size_t)(row0 + 8) * ldc + col) = pack_bf16(a2, a3);
            } else {
                float* C = (float*)Cv;
                *(float2*)(C + (size_t)row0 * ldc + col)       = make_float2(a0, a1);
                *(float2*)(C + (size_t)(row0 + 8) * ldc + col) = make_float2(a2, a3);
            }
        }
    }
}

// ======================= mma.sync flash attention ========================
// (unchanged core; epilogue writes reordered layout for the proj gemm)
#define AT_QS   0
#define AT_KS   18432
#define AT_VS   36864
#define AT_SMEM 55296
#define KVROW   144
#define KVTILE  9216

__global__ __launch_bounds__(256)
void attn_mma()
{
    extern __shared__ __align__(128) char smem[];
    const uint32_t sb = smem_u32(smem);
    const int tid = threadIdx.x, wid = tid >> 5, lane = tid & 31;
    const int q0 = blockIdx.x * 128, h = blockIdx.y, bb = blockIdx.z;

    const uint32_t QS = sb + AT_QS;
    const uint32_t KS = sb + AT_KS;
    const uint32_t VS = sb + AT_VS;

    {
        const __nv_bfloat16* gq = g_qkvb + ((size_t)(bb * SEQ + q0)) * NQKV + h * HDIM;
#pragma unroll
        for (int u = 0; u < 4; u++) {
            int id = tid + u * 256;
            int row = id >> 3, ch = id & 7;
            CP16(QS + row * KVROW + ch * 16, gq + (size_t)row * NQKV + ch * 8);
        }
        CPCOMMIT();
    }
    auto load_kv = [&](int kt, int s) {
        const __nv_bfloat16* gk = g_qkvb + ((size_t)(bb * SEQ + kt * 64)) * NQKV + EMB + h * HDIM;
        const __nv_bfloat16* gv = gk + EMB;
        uint32_t kd = KS + s * KVTILE, vd = VS + s * KVTILE;
#pragma unroll
        for (int u = 0; u < 2; u++) {
            int id = tid + u * 256;
            int row = id >> 3, ch = id & 7;
            CP16(kd + row * KVROW + ch * 16, gk + (size_t)row * NQKV + ch * 8);
            CP16(vd + row * KVROW + ch * 16, gv + (size_t)row * NQKV + ch * 8);
        }
        CPCOMMIT();
    };
    load_kv(0, 0);

    CPWAIT1();
    __syncthreads();

    uint32_t qf[4][4];
#pragma unroll
    for (int t = 0; t < 4; t++) {
        uint32_t addr = QS + (uint32_t)(wid * 16 + (lane & 15)) * KVROW
                      + (uint32_t)(t * 16 + (lane >> 4) * 8) * 2;
        LDSM4(qf[t], addr);
    }
    const __nv_bfloat162 qsc = __floats2bfloat162_rn(0.125f, 0.125f);
#pragma unroll
    for (int t = 0; t < 4; t++)
#pragma unroll
        for (int i = 0; i < 4; i++) {
            __nv_bfloat162 v = *(__nv_bfloat162*)&qf[t][i];
            v = __hmul2(v, qsc);
            qf[t][i] = *(uint32_t*)&v;
        }

    float oa[8][4];
#pragma unroll
    for (int j = 0; j < 8; j++)
#pragma unroll
        for (int c = 0; c < 4; c++) oa[j][c] = 0.f;
    float m0 = -1e30f, m1 = -1e30f, l0 = 0.f, l1 = 0.f;

    for (int kt = 0; kt < SEQ / 64; kt++) {
        if (kt + 1 < SEQ / 64) { load_kv(kt + 1, (kt + 1) & 1); CPWAIT1(); }
        else                   { CPWAIT0(); }
        __syncthreads();
        const uint32_t Kst = KS + (kt & 1) * KVTILE;
        const uint32_t Vst = VS + (kt & 1) * KVTILE;

        float sacc[8][4];
#pragma unroll
        for (int j = 0; j < 8; j++)
#pragma unroll
            for (int c = 0; c < 4; c++) sacc[j][c] = 0.f;
#pragma unroll
        for (int kk = 0; kk < 4; kk++) {
#pragma unroll
            for (int kg = 0; kg < 4; kg++) {
                uint32_t kf[4];
                uint32_t addr = Kst + (uint32_t)(kg * 16 + (lane & 15)) * KVROW
                              + (uint32_t)(kk * 16 + (lane >> 4) * 8) * 2;
                LDSM4(kf, addr);
                MMA16816(sacc[2 * kg],     qf[kk], kf[0], kf[2]);
                MMA16816(sacc[2 * kg + 1], qf[kk], kf[1], kf[3]);
            }
        }

        float mx0 = -1e30f, mx1 = -1e30f;
#pragma unroll
        for (int j = 0; j < 8; j++) {
            mx0 = fmaxf(mx0, fmaxf(sacc[j][0], sacc[j][1]));
            mx1 = fmaxf(mx1, fmaxf(sacc[j][2], sacc[j][3]));
        }
        mx0 = fmaxf(mx0, __shfl_xor_sync(0xffffffffu, mx0, 1));
        mx0 = fmaxf(mx0, __shfl_xor_sync(0xffffffffu, mx0, 2));
        mx1 = fmaxf(mx1, __shfl_xor_sync(0xffffffffu, mx1, 1));
        mx1 = fmaxf(mx1, __shfl_xor_sync(0xffffffffu, mx1, 2));
        float nm0 = fmaxf(m0, mx0), nm1 = fmaxf(m1, mx1);
        float corr0 = __expf(m0 - nm0), corr1 = __expf(m1 - nm1);
        m0 = nm0; m1 = nm1;

        float rs0 = 0.f, rs1 = 0.f;
#pragma unroll
        for (int j = 0; j < 8; j++) {
            sacc[j][0] = __expf(sacc[j][0] - nm0); rs0 += sacc[j][0];
            sacc[j][1] = __expf(sacc[j][1] - nm0); rs0 += sacc[j][1];
            sacc[j][2] = __expf(sacc[j][2] - nm1); rs1 += sacc[j][2];
            sacc[j][3] = __expf(sacc[j][3] - nm1); rs1 += sacc[j][3];
        }
        rs0 += __shfl_xor_sync(0xffffffffu, rs0, 1);
        rs0 += __shfl_xor_sync(0xffffffffu, rs0, 2);
        rs1 += __shfl_xor_sync(0xffffffffu, rs1, 1);
        rs1 += __shfl_xor_sync(0xffffffffu, rs1, 2);
        l0 = l0 * corr0 + rs0;
        l1 = l1 * corr1 + rs1;
#pragma unroll
        for (int j = 0; j < 8; j++) {
            oa[j][0] *= corr0; oa[j][1] *= corr0;
            oa[j][2] *= corr1; oa[j][3] *= corr1;
        }

        uint32_t pf[4][4];
#pragma unroll
        for (int t = 0; t < 4; t++) {
            pf[t][0] = pack_bf16(sacc[2 * t][0],     sacc[2 * t][1]);
            pf[t][1] = pack_bf16(sacc[2 * t][2],     sacc[2 * t][3]);
            pf[t][2] = pack_bf16(sacc[2 * t + 1][0], sacc[2 * t + 1][1]);
            pf[t][3] = pack_bf16(sacc[2 * t + 1][2], sacc[2 * t + 1][3]);
        }

        const int t4 = lane >> 3, lr = lane & 7;
#pragma unroll
        for (int t = 0; t < 4; t++) {
#pragma unroll
            for (int hg = 0; hg < 4; hg++) {
                uint32_t vf[4];
                int key = t * 16 + ((t4 & 1) << 3) + lr;
                int hd  = hg * 16 + ((t4 >> 1) << 3);
                uint32_t addr = Vst + (uint32_t)key * KVROW + (uint32_t)hd * 2;
                LDSM4T(vf, addr);
                MMA16816(oa[2 * hg],     pf[t], vf[0], vf[1]);
                MMA16816(oa[2 * hg + 1], pf[t], vf[2], vf[3]);
            }
        }
        __syncthreads();
    }

    // ---- epilogue: normalize, write bf16 into REORDERED layout ----
    const float inv0 = 1.f / l0, inv1 = 1.f / l1;
    const int r = lane >> 2, cq = (lane & 3) * 2;
    const int row0 = bb * SEQ + q0 + wid * 16 + r;
    char* outb = (char*)g_attr;
#pragma unroll
    for (int jh = 0; jh < 8; jh++) {
        int col = h * HDIM + jh * 8 + cq;
        *(uint32_t*)(outb + reord_off(row0, col)) =
            pack_bf16(oa[jh][0] * inv0, oa[jh][1] * inv0);
        *(uint32_t*)(outb + reord_off(row0 + 8, col)) =
            pack_bf16(oa[jh][2] * inv1, oa[jh][3] * inv1);
    }
}

// ======================= residual + LayerNorm ============================
__global__ __launch_bounds__(256)
void ln_kernel(const float* __restrict__ x, const float* __restrict__ gamma,
               const float* __restrict__ beta, float* __restrict__ out)
{
    const int row = blockIdx.x;
    const int t   = threadIdx.x;
    const size_t off = (size_t)row * EMB + t * 4;

    float4 a = *(const float4*)&g_pj[off];
    float4 r = *(const float4*)&x[off];
    float y0 = a.x + r.x, y1 = a.y + r.y, y2 = a.z + r.z, y3 = a.w + r.w;

    float s  = (y0 + y1) + (y2 + y3);
    float ss = fmaf(y0, y0, fmaf(y1, y1, fmaf(y2, y2, y3 * y3)));

#pragma unroll
    for (int offx = 16; offx > 0; offx >>= 1) {
        s  += __shfl_xor_sync(0xffffffffu, s,  offx);
        ss += __shfl_xor_sync(0xffffffffu, ss, offx);
    }
    __shared__ float sbuf[8], ssbuf[8];
    int lane = t & 31, w = t >> 5;
    if (lane == 0) { sbuf[w] = s; ssbuf[w] = ss; }
    __syncthreads();
    if (w == 0) {
        float sv  = (lane < 8) ? sbuf[lane]  : 0.f;
        float ssv = (lane < 8) ? ssbuf[lane] : 0.f;
#pragma unroll
        for (int offx = 4; offx > 0; offx >>= 1) {
            sv  += __shfl_xor_sync(0xffffffffu, sv,  offx);
            ssv += __shfl_xor_sync(0xffffffffu, ssv, offx);
        }
        if (lane == 0) { sbuf[0] = sv; ssbuf[0] = ssv; }
    }
    __syncthreads();
    float mu  = sbuf[0] * (1.f / EMB);
    float var = ssbuf[0] * (1.f / EMB) - mu * mu;
    float rs  = rsqrtf(var + 1e-5f);

    float4 g  = *(const float4*)&gamma[t * 4];
    float4 be = *(const float4*)&beta[t * 4];
    float4 ov;
    ov.x = (y0 - mu) * rs * g.x + be.x;
    ov.y = (y1 - mu) * rs * g.y + be.y;
    ov.z = (y2 - mu) * rs * g.z + be.z;
    ov.w = (y3 - mu) * rs * g.w + be.w;
    *(float4*)&out[off] = ov;
}

// =========================================================================
extern "C" void kernel_launch(void* const* d_in, const int* in_sizes, int n_in,
                              void* d_out, int out_size)
{
    const float* x      = (const float*)d_in[0];
    const float* W_qkv  = (const float*)d_in[1];
    const float* b_qkv  = (const float*)d_in[2];
    const float* W_proj = (const float*)d_in[3];
    const float* b_proj = (const float*)d_in[4];
    const float* gamma  = (const float*)d_in[5];
    const float* beta   = (const float*)d_in[6];
    float* out = (float*)d_out;

    float* pj_buf;  cudaGetSymbolAddress((void**)&pj_buf,  g_pj);
    __nv_bfloat16 *xr, *wqr, *wpr, *qkvb, *attr;
    cudaGetSymbolAddress((void**)&xr,   g_xr);
    cudaGetSymbolAddress((void**)&wqr,  g_wqr);
    cudaGetSymbolAddress((void**)&wpr,  g_wpr);
    cudaGetSymbolAddress((void**)&qkvb, g_qkvb);
    cudaGetSymbolAddress((void**)&attr, g_attr);

    cudaFuncSetAttribute(gemm_bulk<true>,  cudaFuncAttributeMaxDynamicSharedMemorySize, GEMM_SMEM);
    cudaFuncSetAttribute(gemm_bulk<false>, cudaFuncAttributeMaxDynamicSharedMemorySize, GEMM_SMEM);
    cudaFuncSetAttribute(attn_mma,         cudaFuncAttributeMaxDynamicSharedMemorySize, AT_SMEM);

    // reorder + bf16-convert GEMM inputs
    reord_kernel<<<(MTOT * 128 + 255) / 256, 256>>>(x,      (uint4*)xr,  MTOT * 128);
    reord_kernel<<<(NQKV * 128 + 255) / 256, 256>>>(W_qkv,  (uint4*)wqr, NQKV * 128);
    reord_kernel<<<(EMB  * 128 + 255) / 256, 256>>>(W_proj, (uint4*)wpr, EMB  * 128);

    // 1) QKV projection -> bf16 QKV (row-major, for attention)
    gemm_bulk<true><<<dim3(NQKV / 128, MTOT / 128), 256, GEMM_SMEM>>>(xr, wqr, b_qkv, qkvb, EMB, NQKV);
    // 2) flash attention -> bf16 attn out (reordered, for proj gemm)
    attn_mma<<<dim3(SEQ / 128, HEADS, BATCH), 256, AT_SMEM>>>();
    // 3) output projection -> fp32
    gemm_bulk<false><<<dim3(EMB / 128, MTOT / 128), 256, GEMM_SMEM>>>(attr, wpr, b_proj, pj_buf, EMB, EMB);
    // 4) residual + layernorm
    ln_kernel<<<MTOT, 256>>>(x, gamma, beta, out);
}

// round 7
// speedup vs baseline: 9.7894x; 1.0823x over previous
#include <cuda_runtime.h>
#include <cuda_bf16.h>
#include <math.h>
#include <stdint.h>

#define BATCH 2
#define SEQ   2048
#define EMB   1024
#define HEADS 16
#define HDIM  64
#define MTOT  4096
#define NQKV  3072

// ---------------- scratch (no allocation allowed) ----------------
// head-major, XOR-swizzled bf16: offset(b,h,s,d) = ((b*16+h)*2048+s)*128B
//   + ((d>>3)^(s&7))*16 + (d&7)*2.  Q is pre-scaled by 0.125.
__device__ __align__(256) __nv_bfloat16 g_q[(size_t)BATCH*HEADS*SEQ*HDIM];
__device__ __align__(256) __nv_bfloat16 g_k[(size_t)BATCH*HEADS*SEQ*HDIM];
__device__ __align__(256) __nv_bfloat16 g_v[(size_t)BATCH*HEADS*SEQ*HDIM];
__device__ float g_pj[(size_t)MTOT*EMB];              // fp32 proj out (pre-LN)
// reordered GEMM operands: [block128][kchunk64][row][(c16^(row&7))*16B]
__device__ __align__(256) __nv_bfloat16 g_xr  [(size_t)MTOT*EMB];
__device__ __align__(256) __nv_bfloat16 g_wqr [(size_t)NQKV*EMB];
__device__ __align__(256) __nv_bfloat16 g_wpr [(size_t)EMB*EMB];
__device__ __align__(256) __nv_bfloat16 g_attr[(size_t)MTOT*EMB];

// ======================= PTX helpers (base-target only) ==================
__device__ __forceinline__ uint32_t smem_u32(const void* p) {
    uint32_t a;
    asm("{ .reg .u64 t; cvta.to.shared.u64 t, %1; cvt.u32.u64 %0, t; }" : "=r"(a) : "l"(p));
    return a;
}
#define MBAR_INIT(a, c) asm volatile("mbarrier.init.shared.b64 [%0], %1;" :: "r"(a), "r"(c) : "memory")
#define MBAR_ARRIVE(a)  asm volatile("mbarrier.arrive.shared.b64 _, [%0];" :: "r"(a) : "memory")
#define MBAR_EXPECT(a, n) asm volatile("mbarrier.arrive.expect_tx.shared.b64 _, [%0], %1;" :: "r"(a), "r"(n) : "memory")
#define MBAR_WAIT(a, ph) do {                                                        \
    uint32_t _m = (a); uint32_t _p = (ph); uint32_t _d;                              \
    asm volatile("{ .reg .pred p; mbarrier.try_wait.parity.acquire.cta.shared::cta.b64 p, [%1], %2; selp.b32 %0,1,0,p; }" \
        : "=r"(_d) : "r"(_m), "r"(_p) : "memory");                                   \
    if (!_d) {                                                                       \
        asm volatile("{ .reg .pred P1; WL_%=: mbarrier.try_wait.parity.acquire.cta.shared::cta.b64 P1, [%0], %1, 0x989680; @P1 bra.uni WD_%=; bra.uni WL_%=; WD_%=: }" \
            :: "r"(_m), "r"(_p) : "memory");                                         \
    } } while (0)

#define BULKCP(dst, src, bytes, mbar) \
    asm volatile("cp.async.bulk.shared::cta.global.mbarrier::complete_tx::bytes [%0], [%1], %2, [%3];" \
        :: "r"(dst), "l"(src), "r"(bytes), "r"(mbar) : "memory")

#define LDSM4(r, addr) \
    asm volatile("ldmatrix.sync.aligned.m8n8.x4.shared.b16 {%0,%1,%2,%3}, [%4];" \
        : "=r"((r)[0]), "=r"((r)[1]), "=r"((r)[2]), "=r"((r)[3]) : "r"(addr))
#define LDSM4T(r, addr) \
    asm volatile("ldmatrix.sync.aligned.m8n8.x4.trans.shared.b16 {%0,%1,%2,%3}, [%4];" \
        : "=r"((r)[0]), "=r"((r)[1]), "=r"((r)[2]), "=r"((r)[3]) : "r"(addr))

#define MMA16816(d, a, b0, b1) \
    asm volatile("mma.sync.aligned.m16n8k16.row.col.f32.bf16.bf16.f32 " \
        "{%0,%1,%2,%3}, {%4,%5,%6,%7}, {%8,%9}, {%0,%1,%2,%3};" \
        : "+f"((d)[0]), "+f"((d)[1]), "+f"((d)[2]), "+f"((d)[3]) \
        : "r"((a)[0]), "r"((a)[1]), "r"((a)[2]), "r"((a)[3]), "r"(b0), "r"(b1))

__device__ __forceinline__ uint32_t pack_bf16(float a, float b) {
    __nv_bfloat162 v = __floats2bfloat162_rn(a, b);
    return *(uint32_t*)&v;
}
// byte offset into reordered [R,1024] bf16 matrix (proj gemm A operand)
__device__ __forceinline__ size_t reord_off(int row, int col) {
    int mb = row >> 7, r = row & 127;
    int ch = col >> 6, c16 = (col >> 3) & 7, rem = col & 7;
    return (((size_t)mb * 16 + ch) << 14) + ((size_t)r << 7)
         + ((size_t)(c16 ^ (r & 7)) << 4) + rem * 2;
}

// ======================= reorder: fp32 [R,1024] -> reordered bf16 ========
__global__ __launch_bounds__(256)
void reord_kernel(const float* __restrict__ in, uint4* __restrict__ out, int nunits)
{
    int u = blockIdx.x * 256 + threadIdx.x;
    if (u >= nunits) return;
    int row = u >> 7;
    int cu  = u & 127;
    int ch  = cu >> 3, c16 = cu & 7;
    const float4* src = (const float4*)(in + (size_t)row * 1024 + cu * 8);
    float4 a = src[0], b = src[1];
    uint4 o;
    o.x = pack_bf16(a.x, a.y);  o.y = pack_bf16(a.z, a.w);
    o.z = pack_bf16(b.x, b.y);  o.w = pack_bf16(b.z, b.w);
    int r = row & 127;
    size_t dst = ((size_t)(row >> 7) * 16 + ch) * 1024 + (size_t)r * 8 + (c16 ^ (r & 7));
    out[dst] = o;
}

// ======================= bulk-copy mma.sync GEMM (TN) ====================
// MODE 0: fp32 C.  MODE 1: scatter bf16 into g_q (x0.125) / g_k / g_v.
#define GSTG   32768
#define GEMM_SMEM (1024 + 3*GSTG)

template<int MODE>
__global__ __launch_bounds__(256)
void gemm_bulk(const __nv_bfloat16* __restrict__ A, const __nv_bfloat16* __restrict__ B,
               const float* __restrict__ bias, void* __restrict__ Cv, int K, int ldc)
{
    extern __shared__ __align__(1024) char smem[];
    const uint32_t sb = smem_u32(smem);
    const int tid  = threadIdx.x;
    const int wid  = tid >> 5, lane = tid & 31;
    const int m0   = blockIdx.y * 128, n0 = blockIdx.x * 128;
    const int wm   = (wid >> 2) * 64;
    const int wn   = (wid & 3) * 32;
    const int NCH  = K >> 6;

    const uint32_t full0  = sb;
    const uint32_t empty0 = sb + 24;

    if (tid == 0) {
#pragma unroll
        for (int s = 0; s < 3; s++) { MBAR_INIT(full0 + s * 8, 1); MBAR_INIT(empty0 + s * 8, 8); }
    }
    __syncthreads();

    const char* Ablk = (const char*)A + ((size_t)blockIdx.y * NCH) * 16384;
    const char* Bblk = (const char*)B + ((size_t)blockIdx.x * NCH) * 16384;

    if (tid == 0) {
#pragma unroll
        for (int c = 0; c < 3; c++) {
            MBAR_EXPECT(full0 + c * 8, 32768u);
            uint32_t st = sb + 1024 + c * GSTG;
            BULKCP(st,         Ablk + (size_t)c * 16384, 16384u, full0 + c * 8);
            BULKCP(st + 16384, Bblk + (size_t)c * 16384, 16384u, full0 + c * 8);
        }
    }

    float acc[4][4][4];
#pragma unroll
    for (int i = 0; i < 4; i++)
#pragma unroll
        for (int j = 0; j < 4; j++)
#pragma unroll
            for (int c = 0; c < 4; c++) acc[i][j][c] = 0.f;

    for (int i = 0; i < NCH; i++) {
        const int s = i % 3;
        MBAR_WAIT(full0 + s * 8, (uint32_t)((i / 3) & 1));
        const uint32_t bA = sb + 1024 + s * GSTG;
        const uint32_t bB = bA + 16384;
#pragma unroll
        for (int kk = 0; kk < 4; kk++) {
            uint32_t af[4][4], bfr[2][4];
            const int c16 = kk * 2 + (lane >> 4);
#pragma unroll
            for (int t4 = 0; t4 < 4; t4++) {
                int rr = wm + t4 * 16 + (lane & 15);
                LDSM4(af[t4], bA + (uint32_t)(rr * 128) + (uint32_t)((c16 ^ (rr & 7)) << 4));
            }
#pragma unroll
            for (int t2 = 0; t2 < 2; t2++) {
                int rr = wn + t2 * 16 + (lane & 15);
                LDSM4(bfr[t2], bB + (uint32_t)(rr * 128) + (uint32_t)((c16 ^ (rr & 7)) << 4));
            }
#pragma unroll
            for (int mi = 0; mi < 4; mi++)
#pragma unroll
                for (int nj = 0; nj < 4; nj++) {
                    uint32_t b0 = bfr[nj >> 1][nj & 1];
                    uint32_t b1 = bfr[nj >> 1][(nj & 1) + 2];
                    MMA16816(acc[mi][nj], af[mi], b0, b1);
                }
        }
        if (lane == 0) MBAR_ARRIVE(empty0 + s * 8);
        if (tid == 0 && i + 3 < NCH) {
            const int j = i + 3;
            const int sj = j % 3;
            MBAR_WAIT(empty0 + sj * 8, (uint32_t)((j / 3 - 1) & 1));
            MBAR_EXPECT(full0 + sj * 8, 32768u);
            uint32_t st = sb + 1024 + sj * GSTG;
            BULKCP(st,         Ablk + (size_t)j * 16384, 16384u, full0 + sj * 8);
            BULKCP(st + 16384, Bblk + (size_t)j * 16384, 16384u, full0 + sj * 8);
        }
    }

    const int r  = lane >> 2;
    const int cq = (lane & 3) * 2;
#pragma unroll
    for (int mi = 0; mi < 4; mi++) {
        int row0 = m0 + wm + mi * 16 + r;
#pragma unroll
        for (int nj = 0; nj < 4; nj++) {
            int col = n0 + wn + nj * 8 + cq;
            float2 bv = *(const float2*)(bias + col);
            float a0 = acc[mi][nj][0] + bv.x, a1 = acc[mi][nj][1] + bv.y;
            float a2 = acc[mi][nj][2] + bv.x, a3 = acc[mi][nj][3] + bv.y;
            if (MODE == 1) {
                // scatter into head-major swizzled Q/K/V
                int b  = row0 >> 11, ss = row0 & 2047;
                int cc = col >> 10, rem = col & 1023;
                int h  = rem >> 6,  d  = rem & 63;
                char* base = (cc == 0) ? (char*)g_q : (cc == 1) ? (char*)g_k : (char*)g_v;
                float sc = (cc == 0) ? 0.125f : 1.f;
                size_t off = ((size_t)((b * HEADS + h) * SEQ + ss)) * 128
                           + (size_t)(((d >> 3) ^ (ss & 7)) << 4) + (d & 7) * 2;
                *(uint32_t*)(base + off)           = pack_bf16(a0 * sc, a1 * sc);
                *(uint32_t*)(base + off + 8 * 128) = pack_bf16(a2 * sc, a3 * sc);
            } else {
                float* C = (float*)Cv;
                *(float2*)(C + (size_t)row0 * ldc + col)       = make_float2(a0, a1);
                *(float2*)(C + (size_t)(row0 + 8) * ldc + col) = make_float2(a2, a3);
            }
        }
    }
}

// ======================= bulk-pipelined mma.sync flash attention =========
// 128 thr / 4 warps. 32 q-rows per warp (128/CTA). KV tiles of 64 keys,
// 3-stage cp.async.bulk ring. Q/K/V head-major swizzled bf16 (Q pre-scaled).
#define AT_Q    1024
#define AT_KV   17408                 // 3 stages x (K 8KB + V 8KB)
#define AT_SMEM (AT_KV + 3*16384)     // 66560

__global__ __launch_bounds__(128)
void attn_mma()
{
    extern __shared__ __align__(1024) char smem[];
    const uint32_t sb = smem_u32(smem);
    const int tid = threadIdx.x, wid = tid >> 5, lane = tid & 31;
    const int q0 = blockIdx.x * 128, h = blockIdx.y, bb = blockIdx.z;

    const uint32_t full0  = sb;
    const uint32_t empty0 = sb + 24;
    const uint32_t qbar   = sb + 48;
    const uint32_t QS     = sb + AT_Q;
    const size_t headbase = ((size_t)(bb * HEADS + h) * SEQ) * 128;   // bytes

    if (tid == 0) {
#pragma unroll
        for (int s = 0; s < 3; s++) { MBAR_INIT(full0 + s * 8, 1); MBAR_INIT(empty0 + s * 8, 4); }
        MBAR_INIT(qbar, 1);
    }
    __syncthreads();

    if (tid == 0) {
        MBAR_EXPECT(qbar, 16384u);
        BULKCP(QS, (const char*)g_q + headbase + (size_t)q0 * 128, 16384u, qbar);
#pragma unroll
        for (int c = 0; c < 3; c++) {
            MBAR_EXPECT(full0 + c * 8, 16384u);
            uint32_t st = sb + AT_KV + c * 16384;
            BULKCP(st,        (const char*)g_k + headbase + (size_t)(c * 64) * 128, 8192u, full0 + c * 8);
            BULKCP(st + 8192, (const char*)g_v + headbase + (size_t)(c * 64) * 128, 8192u, full0 + c * 8);
        }
    }
    MBAR_WAIT(qbar, 0u);

    float oa[2][8][4];
#pragma unroll
    for (int mi = 0; mi < 2; mi++)
#pragma unroll
        for (int j = 0; j < 8; j++)
#pragma unroll
            for (int c = 0; c < 4; c++) oa[mi][j][c] = 0.f;
    float mrow[4] = {-1e30f, -1e30f, -1e30f, -1e30f};
    float lrow[4] = {0.f, 0.f, 0.f, 0.f};

    for (int kt = 0; kt < SEQ / 64; kt++) {
        const int s = kt % 3;
        MBAR_WAIT(full0 + s * 8, (uint32_t)((kt / 3) & 1));
        const uint32_t Kst = sb + AT_KV + s * 16384;
        const uint32_t Vst = Kst + 8192;

        // ---- S = Q * K^T ----
        float sacc[2][8][4];
#pragma unroll
        for (int mi = 0; mi < 2; mi++)
#pragma unroll
            for (int j = 0; j < 8; j++)
#pragma unroll
                for (int c = 0; c < 4; c++) sacc[mi][j][c] = 0.f;
#pragma unroll
        for (int kk = 0; kk < 4; kk++) {
            const int c16 = kk * 2 + (lane >> 4);
            uint32_t qf[2][4];
#pragma unroll
            for (int mi = 0; mi < 2; mi++) {
                int qr = wid * 32 + mi * 16 + (lane & 15);
                LDSM4(qf[mi], QS + (uint32_t)(qr * 128) + (uint32_t)((c16 ^ (qr & 7)) << 4));
            }
#pragma unroll
            for (int kg = 0; kg < 4; kg++) {
                uint32_t kf[4];
                int kr = kg * 16 + (lane & 15);
                LDSM4(kf, Kst + (uint32_t)(kr * 128) + (uint32_t)((c16 ^ (kr & 7)) << 4));
#pragma unroll
                for (int mi = 0; mi < 2; mi++) {
                    MMA16816(sacc[mi][2 * kg],     qf[mi], kf[0], kf[2]);
                    MMA16816(sacc[mi][2 * kg + 1], qf[mi], kf[1], kf[3]);
                }
            }
        }

        // ---- online softmax + P pack ----
        uint32_t pf[2][4][4];
#pragma unroll
        for (int mi = 0; mi < 2; mi++) {
            float mx0 = -1e30f, mx1 = -1e30f;
#pragma unroll
            for (int j = 0; j < 8; j++) {
                mx0 = fmaxf(mx0, fmaxf(sacc[mi][j][0], sacc[mi][j][1]));
                mx1 = fmaxf(mx1, fmaxf(sacc[mi][j][2], sacc[mi][j][3]));
            }
            mx0 = fmaxf(mx0, __shfl_xor_sync(0xffffffffu, mx0, 1));
            mx0 = fmaxf(mx0, __shfl_xor_sync(0xffffffffu, mx0, 2));
            mx1 = fmaxf(mx1, __shfl_xor_sync(0xffffffffu, mx1, 1));
            mx1 = fmaxf(mx1, __shfl_xor_sync(0xffffffffu, mx1, 2));
            float nm0 = fmaxf(mrow[2 * mi], mx0), nm1 = fmaxf(mrow[2 * mi + 1], mx1);
            float corr0 = __expf(mrow[2 * mi] - nm0), corr1 = __expf(mrow[2 * mi + 1] - nm1);
            mrow[2 * mi] = nm0; mrow[2 * mi + 1] = nm1;

            float rs0 = 0.f, rs1 = 0.f;
#pragma unroll
            for (int j = 0; j < 8; j++) {
                sacc[mi][j][0] = __expf(sacc[mi][j][0] - nm0); rs0 += sacc[mi][j][0];
                sacc[mi][j][1] = __expf(sacc[mi][j][1] - nm0); rs0 += sacc[mi][j][1];
                sacc[mi][j][2] = __expf(sacc[mi][j][2] - nm1); rs1 += sacc[mi][j][2];
                sacc[mi][j][3] = __expf(sacc[mi][j][3] - nm1); rs1 += sacc[mi][j][3];
            }
            rs0 += __shfl_xor_sync(0xffffffffu, rs0, 1);
            rs0 += __shfl_xor_sync(0xffffffffu, rs0, 2);
            rs1 += __shfl_xor_sync(0xffffffffu, rs1, 1);
            rs1 += __shfl_xor_sync(0xffffffffu, rs1, 2);
            lrow[2 * mi]     = lrow[2 * mi]     * corr0 + rs0;
            lrow[2 * mi + 1] = lrow[2 * mi + 1] * corr1 + rs1;
#pragma unroll
            for (int j = 0; j < 8; j++) {
                oa[mi][j][0] *= corr0; oa[mi][j][1] *= corr0;
                oa[mi][j][2] *= corr1; oa[mi][j][3] *= corr1;
            }
#pragma unroll
            for (int t = 0; t < 4; t++) {
                pf[mi][t][0] = pack_bf16(sacc[mi][2 * t][0],     sacc[mi][2 * t][1]);
                pf[mi][t][1] = pack_bf16(sacc[mi][2 * t][2],     sacc[mi][2 * t][3]);
                pf[mi][t][2] = pack_bf16(sacc[mi][2 * t + 1][0], sacc[mi][2 * t + 1][1]);
                pf[mi][t][3] = pack_bf16(sacc[mi][2 * t + 1][2], sacc[mi][2 * t + 1][3]);
            }
        }

        // ---- O += P * V ----
        const int t4 = lane >> 3, lr = lane & 7;
#pragma unroll
        for (int t = 0; t < 4; t++) {
#pragma unroll
            for (int hg = 0; hg < 4; hg++) {
                uint32_t vf[4];
                int key = t * 16 + ((t4 & 1) << 3) + lr;
                int c16 = hg * 2 + (t4 >> 1);
                LDSM4T(vf, Vst + (uint32_t)(key * 128) + (uint32_t)((c16 ^ (key & 7)) << 4));
#pragma unroll
                for (int mi = 0; mi < 2; mi++) {
                    MMA16816(oa[mi][2 * hg],     pf[mi][t], vf[0], vf[1]);
                    MMA16816(oa[mi][2 * hg + 1], pf[mi][t], vf[2], vf[3]);
                }
            }
        }

        if (lane == 0) MBAR_ARRIVE(empty0 + s * 8);
        if (tid == 0 && kt + 3 < SEQ / 64) {
            const int j = kt + 3;
            const int sj = j % 3;
            MBAR_WAIT(empty0 + sj * 8, (uint32_t)((j / 3 - 1) & 1));
            MBAR_EXPECT(full0 + sj * 8, 16384u);
            uint32_t st = sb + AT_KV + sj * 16384;
            BULKCP(st,        (const char*)g_k + headbase + (size_t)(j * 64) * 128, 8192u, full0 + sj * 8);
            BULKCP(st + 8192, (const char*)g_v + headbase + (size_t)(j * 64) * 128, 8192u, full0 + sj * 8);
        }
    }

    // ---- epilogue: normalize, write bf16 into reordered layout ----
    const int r = lane >> 2, cq = (lane & 3) * 2;
    char* outb = (char*)g_attr;
#pragma unroll
    for (int mi = 0; mi < 2; mi++) {
        float inv0 = 1.f / lrow[2 * mi], inv1 = 1.f / lrow[2 * mi + 1];
        int row0 = bb * SEQ + q0 + wid * 32 + mi * 16 + r;
#pragma unroll
        for (int jh = 0; jh < 8; jh++) {
            int col = h * HDIM + jh * 8 + cq;
            *(uint32_t*)(outb + reord_off(row0, col)) =
                pack_bf16(oa[mi][jh][0] * inv0, oa[mi][jh][1] * inv0);
            *(uint32_t*)(outb + reord_off(row0 + 8, col)) =
                pack_bf16(oa[mi][jh][2] * inv1, oa[mi][jh][3] * inv1);
        }
    }
}

// ======================= residual + LayerNorm ============================
__global__ __launch_bounds__(256)
void ln_kernel(const float* __restrict__ x, const float* __restrict__ gamma,
               const float* __restrict__ beta, float* __restrict__ out)
{
    const int row = blockIdx.x;
    const int t   = threadIdx.x;
    const size_t off = (size_t)row * EMB + t * 4;

    float4 a = *(const float4*)&g_pj[off];
    float4 r = *(const float4*)&x[off];
    float y0 = a.x + r.x, y1 = a.y + r.y, y2 = a.z + r.z, y3 = a.w + r.w;

    float s  = (y0 + y1) + (y2 + y3);
    float ss = fmaf(y0, y0, fmaf(y1, y1, fmaf(y2, y2, y3 * y3)));

#pragma unroll
    for (int offx = 16; offx > 0; offx >>= 1) {
        s  += __shfl_xor_sync(0xffffffffu, s,  offx);
        ss += __shfl_xor_sync(0xffffffffu, ss, offx);
    }
    __shared__ float sbuf[8], ssbuf[8];
    int lane = t & 31, w = t >> 5;
    if (lane == 0) { sbuf[w] = s; ssbuf[w] = ss; }
    __syncthreads();
    if (w == 0) {
        float sv  = (lane < 8) ? sbuf[lane]  : 0.f;
        float ssv = (lane < 8) ? ssbuf[lane] : 0.f;
#pragma unroll
        for (int offx = 4; offx > 0; offx >>= 1) {
            sv  += __shfl_xor_sync(0xffffffffu, sv,  offx);
            ssv += __shfl_xor_sync(0xffffffffu, ssv, offx);
        }
        if (lane == 0) { sbuf[0] = sv; ssbuf[0] = ssv; }
    }
    __syncthreads();
    float mu  = sbuf[0] * (1.f / EMB);
    float var = ssbuf[0] * (1.f / EMB) - mu * mu;
    float rs  = rsqrtf(var + 1e-5f);

    float4 g  = *(const float4*)&gamma[t * 4];
    float4 be = *(const float4*)&beta[t * 4];
    float4 ov;
    ov.x = (y0 - mu) * rs * g.x + be.x;
    ov.y = (y1 - mu) * rs * g.y + be.y;
    ov.z = (y2 - mu) * rs * g.z + be.z;
    ov.w = (y3 - mu) * rs * g.w + be.w;
    *(float4*)&out[off] = ov;
}

// =========================================================================
extern "C" void kernel_launch(void* const* d_in, const int* in_sizes, int n_in,
                              void* d_out, int out_size)
{
    const float* x      = (const float*)d_in[0];
    const float* W_qkv  = (const float*)d_in[1];
    const float* b_qkv  = (const float*)d_in[2];
    const float* W_proj = (const float*)d_in[3];
    const float* b_proj = (const float*)d_in[4];
    const float* gamma  = (const float*)d_in[5];
    const float* beta   = (const float*)d_in[6];
    float* out = (float*)d_out;

    float* pj_buf;  cudaGetSymbolAddress((void**)&pj_buf,  g_pj);
    __nv_bfloat16 *xr, *wqr, *wpr, *attr;
    cudaGetSymbolAddress((void**)&xr,   g_xr);
    cudaGetSymbolAddress((void**)&wqr,  g_wqr);
    cudaGetSymbolAddress((void**)&wpr,  g_wpr);
    cudaGetSymbolAddress((void**)&attr, g_attr);

    cudaFuncSetAttribute(gemm_bulk<1>, cudaFuncAttributeMaxDynamicSharedMemorySize, GEMM_SMEM);
    cudaFuncSetAttribute(gemm_bulk<0>, cudaFuncAttributeMaxDynamicSharedMemorySize, GEMM_SMEM);
    cudaFuncSetAttribute(attn_mma,     cudaFuncAttributeMaxDynamicSharedMemorySize, AT_SMEM);

    // reorder + bf16-convert GEMM inputs
    reord_kernel<<<(MTOT * 128 + 255) / 256, 256>>>(x,      (uint4*)xr,  MTOT * 128);
    reord_kernel<<<(NQKV * 128 + 255) / 256, 256>>>(W_qkv,  (uint4*)wqr, NQKV * 128);
    reord_kernel<<<(EMB  * 128 + 255) / 256, 256>>>(W_proj, (uint4*)wpr, EMB  * 128);

    // 1) QKV projection -> head-major swizzled Q/K/V (Q pre-scaled)
    gemm_bulk<1><<<dim3(NQKV / 128, MTOT / 128), 256, GEMM_SMEM>>>(xr, wqr, b_qkv, nullptr, EMB, NQKV);
    // 2) flash attention -> bf16 attn out (reordered for proj gemm)
    attn_mma<<<dim3(SEQ / 128, HEADS, BATCH), 128, AT_SMEM>>>();
    // 3) output projection -> fp32
    gemm_bulk<0><<<dim3(EMB / 128, MTOT / 128), 256, GEMM_SMEM>>>(attr, wpr, b_proj, pj_buf, EMB, EMB);
    // 4) residual + layernorm
    ln_kernel<<<MTOT, 256>>>(x, gamma, beta, out);
}

// round 8
// speedup vs baseline: 9.9651x; 1.0180x over previous
#include <cuda_runtime.h>
#include <cuda_bf16.h>
#include <math.h>
#include <stdint.h>

#define BATCH 2
#define SEQ   2048
#define EMB   1024
#define HEADS 16
#define HDIM  64
#define MTOT  4096
#define NQKV  3072

// ---------------- scratch (no allocation allowed) ----------------
// head-major, XOR-swizzled bf16: offset(b,h,s,d) = ((b*16+h)*2048+s)*128B
//   + ((d>>3)^(s&7))*16 + (d&7)*2.  Q is pre-scaled by 0.125.
__device__ __align__(256) __nv_bfloat16 g_q[(size_t)BATCH*HEADS*SEQ*HDIM];
__device__ __align__(256) __nv_bfloat16 g_k[(size_t)BATCH*HEADS*SEQ*HDIM];
__device__ __align__(256) __nv_bfloat16 g_v[(size_t)BATCH*HEADS*SEQ*HDIM];
__device__ float g_pj[(size_t)MTOT*EMB];              // fp32 proj out (pre-LN)
// reordered GEMM operands: [block128][kchunk64][row][(c16^(row&7))*16B]
__device__ __align__(256) __nv_bfloat16 g_xr  [(size_t)MTOT*EMB];
__device__ __align__(256) __nv_bfloat16 g_wqr [(size_t)NQKV*EMB];
__device__ __align__(256) __nv_bfloat16 g_wpr [(size_t)EMB*EMB];
__device__ __align__(256) __nv_bfloat16 g_attr[(size_t)MTOT*EMB];

// ======================= PTX helpers (base-target only) ==================
__device__ __forceinline__ uint32_t smem_u32(const void* p) {
    uint32_t a;
    asm("{ .reg .u64 t; cvta.to.shared.u64 t, %1; cvt.u32.u64 %0, t; }" : "=r"(a) : "l"(p));
    return a;
}
#define MBAR_INIT(a, c) asm volatile("mbarrier.init.shared.b64 [%0], %1;" :: "r"(a), "r"(c) : "memory")
#define MBAR_ARRIVE(a)  asm volatile("mbarrier.arrive.shared.b64 _, [%0];" :: "r"(a) : "memory")
#define MBAR_EXPECT(a, n) asm volatile("mbarrier.arrive.expect_tx.shared.b64 _, [%0], %1;" :: "r"(a), "r"(n) : "memory")
#define MBAR_WAIT(a, ph) do {                                                        \
    uint32_t _m = (a); uint32_t _p = (ph); uint32_t _d;                              \
    asm volatile("{ .reg .pred p; mbarrier.try_wait.parity.acquire.cta.shared::cta.b64 p, [%1], %2; selp.b32 %0,1,0,p; }" \
        : "=r"(_d) : "r"(_m), "r"(_p) : "memory");                                   \
    if (!_d) {                                                                       \
        asm volatile("{ .reg .pred P1; WL_%=: mbarrier.try_wait.parity.acquire.cta.shared::cta.b64 P1, [%0], %1, 0x989680; @P1 bra.uni WD_%=; bra.uni WL_%=; WD_%=: }" \
            :: "r"(_m), "r"(_p) : "memory");                                         \
    } } while (0)

#define BULKCP(dst, src, bytes, mbar) \
    asm volatile("cp.async.bulk.shared::cta.global.mbarrier::complete_tx::bytes [%0], [%1], %2, [%3];" \
        :: "r"(dst), "l"(src), "r"(bytes), "r"(mbar) : "memory")

#define LDSM4(r, addr) \
    asm volatile("ldmatrix.sync.aligned.m8n8.x4.shared.b16 {%0,%1,%2,%3}, [%4];" \
        : "=r"((r)[0]), "=r"((r)[1]), "=r"((r)[2]), "=r"((r)[3]) : "r"(addr))
#define LDSM4T(r, addr) \
    asm volatile("ldmatrix.sync.aligned.m8n8.x4.trans.shared.b16 {%0,%1,%2,%3}, [%4];" \
        : "=r"((r)[0]), "=r"((r)[1]), "=r"((r)[2]), "=r"((r)[3]) : "r"(addr))

#define MMA16816(d, a, b0, b1) \
    asm volatile("mma.sync.aligned.m16n8k16.row.col.f32.bf16.bf16.f32 " \
        "{%0,%1,%2,%3}, {%4,%5,%6,%7}, {%8,%9}, {%0,%1,%2,%3};" \
        : "+f"((d)[0]), "+f"((d)[1]), "+f"((d)[2]), "+f"((d)[3]) \
        : "r"((a)[0]), "r"((a)[1]), "r"((a)[2]), "r"((a)[3]), "r"(b0), "r"(b1))

__device__ __forceinline__ uint32_t pack_bf16(float a, float b) {
    __nv_bfloat162 v = __floats2bfloat162_rn(a, b);
    return *(uint32_t*)&v;
}
// byte offset into reordered [R,1024] bf16 matrix (proj gemm A operand)
__device__ __forceinline__ size_t reord_off(int row, int col) {
    int mb = row >> 7, r = row & 127;
    int ch = col >> 6, c16 = (col >> 3) & 7, rem = col & 7;
    return (((size_t)mb * 16 + ch) << 14) + ((size_t)r << 7)
         + ((size_t)(c16 ^ (r & 7)) << 4) + rem * 2;
}

// ======================= reorder: fp32 [R,1024] -> reordered bf16 ========
__global__ __launch_bounds__(256)
void reord_kernel(const float* __restrict__ in, uint4* __restrict__ out, int nunits)
{
    int u = blockIdx.x * 256 + threadIdx.x;
    if (u >= nunits) return;
    int row = u >> 7;
    int cu  = u & 127;
    int ch  = cu >> 3, c16 = cu & 7;
    const float4* src = (const float4*)(in + (size_t)row * 1024 + cu * 8);
    float4 a = src[0], b = src[1];
    uint4 o;
    o.x = pack_bf16(a.x, a.y);  o.y = pack_bf16(a.z, a.w);
    o.z = pack_bf16(b.x, b.y);  o.w = pack_bf16(b.z, b.w);
    int r = row & 127;
    size_t dst = ((size_t)(row >> 7) * 16 + ch) * 1024 + (size_t)r * 8 + (c16 ^ (r & 7));
    out[dst] = o;
}

// ======================= bulk-copy mma.sync GEMM (TN) ====================
// CTA tile 256(M) x 128(N); 8 warps at 64x64 (4x2). 4-stage bulk pipeline.
// MODE 0: fp32 C.  MODE 1: scatter bf16 into g_q (x0.125) / g_k / g_v.
#define ASLAB  32768
#define BSLAB  16384
#define STGB   (ASLAB + BSLAB)              // 49152
#define GEMM_SMEM (1024 + 4*STGB)           // 197632

template<int MODE>
__global__ __launch_bounds__(256)
void gemm_bulk(const __nv_bfloat16* __restrict__ A, const __nv_bfloat16* __restrict__ B,
               const float* __restrict__ bias, void* __restrict__ Cv, int K, int ldc)
{
    extern __shared__ __align__(1024) char smem[];
    const uint32_t sb = smem_u32(smem);
    const int tid  = threadIdx.x;
    const int wid  = tid >> 5, lane = tid & 31;
    const int m0   = blockIdx.y * 256, n0 = blockIdx.x * 128;
    const int wm   = (wid >> 1) * 64;
    const int wn   = (wid & 1) * 64;
    const int NCH  = K >> 6;

    const uint32_t full0  = sb;           // 4 x 8B
    const uint32_t empty0 = sb + 32;      // 4 x 8B

    if (tid == 0) {
#pragma unroll
        for (int s = 0; s < 4; s++) { MBAR_INIT(full0 + s * 8, 1); MBAR_INIT(empty0 + s * 8, 8); }
    }
    __syncthreads();

    // A slab chunk c: rows 0-127 from block 2*by chunk c, rows 128-255 from block 2*by+1
    const char* AblkL = (const char*)A + ((size_t)(2 * blockIdx.y)     * NCH) * 16384;
    const char* AblkH = (const char*)A + ((size_t)(2 * blockIdx.y + 1) * NCH) * 16384;
    const char* Bblk  = (const char*)B + ((size_t)blockIdx.x * NCH) * 16384;

    if (tid == 0) {
#pragma unroll
        for (int c = 0; c < 4; c++) {
            MBAR_EXPECT(full0 + c * 8, (uint32_t)STGB);
            uint32_t st = sb + 1024 + c * STGB;
            BULKCP(st,         AblkL + (size_t)c * 16384, 16384u, full0 + c * 8);
            BULKCP(st + 16384, AblkH + (size_t)c * 16384, 16384u, full0 + c * 8);
            BULKCP(st + ASLAB, Bblk  + (size_t)c * 16384, 16384u, full0 + c * 8);
        }
    }

    float acc[4][8][4];
#pragma unroll
    for (int i = 0; i < 4; i++)
#pragma unroll
        for (int j = 0; j < 8; j++)
#pragma unroll
            for (int c = 0; c < 4; c++) acc[i][j][c] = 0.f;

    for (int i = 0; i < NCH; i++) {
        const int s = i & 3;
        MBAR_WAIT(full0 + s * 8, (uint32_t)((i >> 2) & 1));
        const uint32_t bA = sb + 1024 + s * STGB;
        const uint32_t bB = bA + ASLAB;
#pragma unroll
        for (int kk = 0; kk < 4; kk++) {
            uint32_t af[4][4], bfr[4][4];
            const int c16 = kk * 2 + (lane >> 4);
#pragma unroll
            for (int t4 = 0; t4 < 4; t4++) {
                int rr = wm + t4 * 16 + (lane & 15);
                LDSM4(af[t4], bA + (uint32_t)(rr * 128) + (uint32_t)((c16 ^ (rr & 7)) << 4));
            }
#pragma unroll
            for (int t4 = 0; t4 < 4; t4++) {
                int rr = wn + t4 * 16 + (lane & 15);
                LDSM4(bfr[t4], bB + (uint32_t)(rr * 128) + (uint32_t)((c16 ^ (rr & 7)) << 4));
            }
#pragma unroll
            for (int mi = 0; mi < 4; mi++)
#pragma unroll
                for (int nj = 0; nj < 8; nj++) {
                    uint32_t b0 = bfr[nj >> 1][nj & 1];
                    uint32_t b1 = bfr[nj >> 1][(nj & 1) + 2];
                    MMA16816(acc[mi][nj], af[mi], b0, b1);
                }
        }
        if (lane == 0) MBAR_ARRIVE(empty0 + s * 8);
        if (tid == 0 && i + 4 < NCH) {
            const int j = i + 4;
            const int sj = j & 3;
            MBAR_WAIT(empty0 + sj * 8, (uint32_t)(((j >> 2) - 1) & 1));
            MBAR_EXPECT(full0 + sj * 8, (uint32_t)STGB);
            uint32_t st = sb + 1024 + sj * STGB;
            BULKCP(st,         AblkL + (size_t)j * 16384, 16384u, full0 + sj * 8);
            BULKCP(st + 16384, AblkH + (size_t)j * 16384, 16384u, full0 + sj * 8);
            BULKCP(st + ASLAB, Bblk  + (size_t)j * 16384, 16384u, full0 + sj * 8);
        }
    }

    const int r  = lane >> 2;
    const int cq = (lane & 3) * 2;
#pragma unroll
    for (int mi = 0; mi < 4; mi++) {
        int row0 = m0 + wm + mi * 16 + r;
#pragma unroll
        for (int nj = 0; nj < 8; nj++) {
            int col = n0 + wn + nj * 8 + cq;
            float2 bv = *(const float2*)(bias + col);
            float a0 = acc[mi][nj][0] + bv.x, a1 = acc[mi][nj][1] + bv.y;
            float a2 = acc[mi][nj][2] + bv.x, a3 = acc[mi][nj][3] + bv.y;
            if (MODE == 1) {
                int b  = row0 >> 11, ss = row0 & 2047;
                int cc = col >> 10, rem = col & 1023;
                int h  = rem >> 6,  d  = rem & 63;
                char* base = (cc == 0) ? (char*)g_q : (cc == 1) ? (char*)g_k : (char*)g_v;
                float sc = (cc == 0) ? 0.125f : 1.f;
                size_t off = ((size_t)((b * HEADS + h) * SEQ + ss)) * 128
                           + (size_t)(((d >> 3) ^ (ss & 7)) << 4) + (d & 7) * 2;
                *(uint32_t*)(base + off)           = pack_bf16(a0 * sc, a1 * sc);
                *(uint32_t*)(base + off + 8 * 128) = pack_bf16(a2 * sc, a3 * sc);
            } else {
                float* C = (float*)Cv;
                *(float2*)(C + (size_t)row0 * ldc + col)       = make_float2(a0, a1);
                *(float2*)(C + (size_t)(row0 + 8) * ldc + col) = make_float2(a2, a3);
            }
        }
    }
}

// ======================= bulk-pipelined mma.sync flash attention =========
// 128 thr / 4 warps. 32 q-rows/warp. KV tiles of 64 keys, 3-stage bulk ring.
// Q fragments held in registers for the whole kernel.
#define AT_Q    1024
#define AT_KV   17408
#define AT_SMEM (AT_KV + 3*16384)     // 66560

__global__ __launch_bounds__(128)
void attn_mma()
{
    extern __shared__ __align__(1024) char smem[];
    const uint32_t sb = smem_u32(smem);
    const int tid = threadIdx.x, wid = tid >> 5, lane = tid & 31;
    const int q0 = blockIdx.x * 128, h = blockIdx.y, bb = blockIdx.z;

    const uint32_t full0  = sb;
    const uint32_t empty0 = sb + 24;
    const uint32_t qbar   = sb + 48;
    const uint32_t QS     = sb + AT_Q;
    const size_t headbase = ((size_t)(bb * HEADS + h) * SEQ) * 128;

    if (tid == 0) {
#pragma unroll
        for (int s = 0; s < 3; s++) { MBAR_INIT(full0 + s * 8, 1); MBAR_INIT(empty0 + s * 8, 4); }
        MBAR_INIT(qbar, 1);
    }
    __syncthreads();

    if (tid == 0) {
        MBAR_EXPECT(qbar, 16384u);
        BULKCP(QS, (const char*)g_q + headbase + (size_t)q0 * 128, 16384u, qbar);
#pragma unroll
        for (int c = 0; c < 3; c++) {
            MBAR_EXPECT(full0 + c * 8, 16384u);
            uint32_t st = sb + AT_KV + c * 16384;
            BULKCP(st,        (const char*)g_k + headbase + (size_t)(c * 64) * 128, 8192u, full0 + c * 8);
            BULKCP(st + 8192, (const char*)g_v + headbase + (size_t)(c * 64) * 128, 8192u, full0 + c * 8);
        }
    }
    MBAR_WAIT(qbar, 0u);

    // Q fragments once, kept in registers
    uint32_t qf[4][2][4];
#pragma unroll
    for (int kk = 0; kk < 4; kk++) {
        const int c16 = kk * 2 + (lane >> 4);
#pragma unroll
        for (int mi = 0; mi < 2; mi++) {
            int qr = wid * 32 + mi * 16 + (lane & 15);
            LDSM4(qf[kk][mi], QS + (uint32_t)(qr * 128) + (uint32_t)((c16 ^ (qr & 7)) << 4));
        }
    }

    float oa[2][8][4];
#pragma unroll
    for (int mi = 0; mi < 2; mi++)
#pragma unroll
        for (int j = 0; j < 8; j++)
#pragma unroll
            for (int c = 0; c < 4; c++) oa[mi][j][c] = 0.f;
    float mrow[4] = {-1e30f, -1e30f, -1e30f, -1e30f};
    float lrow[4] = {0.f, 0.f, 0.f, 0.f};

    for (int kt = 0; kt < SEQ / 64; kt++) {
        const int s = kt % 3;
        MBAR_WAIT(full0 + s * 8, (uint32_t)((kt / 3) & 1));
        const uint32_t Kst = sb + AT_KV + s * 16384;
        const uint32_t Vst = Kst + 8192;

        // ---- S = Q * K^T ----
        float sacc[2][8][4];
#pragma unroll
        for (int mi = 0; mi < 2; mi++)
#pragma unroll
            for (int j = 0; j < 8; j++)
#pragma unroll
                for (int c = 0; c < 4; c++) sacc[mi][j][c] = 0.f;
#pragma unroll
        for (int kk = 0; kk < 4; kk++) {
            const int c16 = kk * 2 + (lane >> 4);
#pragma unroll
            for (int kg = 0; kg < 4; kg++) {
                uint32_t kf[4];
                int kr = kg * 16 + (lane & 15);
                LDSM4(kf, Kst + (uint32_t)(kr * 128) + (uint32_t)((c16 ^ (kr & 7)) << 4));
#pragma unroll
                for (int mi = 0; mi < 2; mi++) {
                    MMA16816(sacc[mi][2 * kg],     qf[kk][mi], kf[0], kf[2]);
                    MMA16816(sacc[mi][2 * kg + 1], qf[kk][mi], kf[1], kf[3]);
                }
            }
        }

        // ---- online softmax + P pack ----
        uint32_t pf[2][4][4];
#pragma unroll
        for (int mi = 0; mi < 2; mi++) {
            float mx0 = -1e30f, mx1 = -1e30f;
#pragma unroll
            for (int j = 0; j < 8; j++) {
                mx0 = fmaxf(mx0, fmaxf(sacc[mi][j][0], sacc[mi][j][1]));
                mx1 = fmaxf(mx1, fmaxf(sacc[mi][j][2], sacc[mi][j][3]));
            }
            mx0 = fmaxf(mx0, __shfl_xor_sync(0xffffffffu, mx0, 1));
            mx0 = fmaxf(mx0, __shfl_xor_sync(0xffffffffu, mx0, 2));
            mx1 = fmaxf(mx1, __shfl_xor_sync(0xffffffffu, mx1, 1));
            mx1 = fmaxf(mx1, __shfl_xor_sync(0xffffffffu, mx1, 2));
            float nm0 = fmaxf(mrow[2 * mi], mx0), nm1 = fmaxf(mrow[2 * mi + 1], mx1);
            float corr0 = __expf(mrow[2 * mi] - nm0), corr1 = __expf(mrow[2 * mi + 1] - nm1);
            mrow[2 * mi] = nm0; mrow[2 * mi + 1] = nm1;

            float rs0 = 0.f, rs1 = 0.f;
#pragma unroll
            for (int j = 0; j < 8; j++) {
                sacc[mi][j][0] = __expf(sacc[mi][j][0] - nm0); rs0 += sacc[mi][j][0];
                sacc[mi][j][1] = __expf(sacc[mi][j][1] - nm0); rs0 += sacc[mi][j][1];
                sacc[mi][j][2] = __expf(sacc[mi][j][2] - nm1); rs1 += sacc[mi][j][2];
                sacc[mi][j][3] = __expf(sacc[mi][j][3] - nm1); rs1 += sacc[mi][j][3];
            }
            rs0 += __shfl_xor_sync(0xffffffffu, rs0, 1);
            rs0 += __shfl_xor_sync(0xffffffffu, rs0, 2);
            rs1 += __shfl_xor_sync(0xffffffffu, rs1, 1);
            rs1 += __shfl_xor_sync(0xffffffffu, rs1, 2);
            lrow[2 * mi]     = lrow[2 * mi]     * corr0 + rs0;
            lrow[2 * mi + 1] = lrow[2 * mi + 1] * corr1 + rs1;
#pragma unroll
            for (int j = 0; j < 8; j++) {
                oa[mi][j][0] *= corr0; oa[mi][j][1] *= corr0;
                oa[mi][j][2] *= corr1; oa[mi][j][3] *= corr1;
            }
#pragma unroll
            for (int t = 0; t < 4; t++) {
                pf[mi][t][0] = pack_bf16(sacc[mi][2 * t][0],     sacc[mi][2 * t][1]);
                pf[mi][t][1] = pack_bf16(sacc[mi][2 * t][2],     sacc[mi][2 * t][3]);
                pf[mi][t][2] = pack_bf16(sacc[mi][2 * t + 1][0], sacc[mi][2 * t + 1][1]);
                pf[mi][t][3] = pack_bf16(sacc[mi][2 * t + 1][2], sacc[mi][2 * t + 1][3]);
            }
        }

        // ---- O += P * V ----
        const int t4 = lane >> 3, lr = lane & 7;
#pragma unroll
        for (int t = 0; t < 4; t++) {
#pragma unroll
            for (int hg = 0; hg < 4; hg++) {
                uint32_t vf[4];
                int key = t * 16 + ((t4 & 1) << 3) + lr;
                int c16 = hg * 2 + (t4 >> 1);
                LDSM4T(vf, Vst + (uint32_t)(key * 128) + (uint32_t)((c16 ^ (key & 7)) << 4));
#pragma unroll
                for (int mi = 0; mi < 2; mi++) {
                    MMA16816(oa[mi][2 * hg],     pf[mi][t], vf[0], vf[1]);
                    MMA16816(oa[mi][2 * hg + 1], pf[mi][t], vf[2], vf[3]);
                }
            }
        }

        if (lane == 0) MBAR_ARRIVE(empty0 + s * 8);
        if (tid == 0 && kt + 3 < SEQ / 64) {
            const int j = kt + 3;
            const int sj = j % 3;
            MBAR_WAIT(empty0 + sj * 8, (uint32_t)((j / 3 - 1) & 1));
            MBAR_EXPECT(full0 + sj * 8, 16384u);
            uint32_t st = sb + AT_KV + sj * 16384;
            BULKCP(st,        (const char*)g_k + headbase + (size_t)(j * 64) * 128, 8192u, full0 + sj * 8);
            BULKCP(st + 8192, (const char*)g_v + headbase + (size_t)(j * 64) * 128, 8192u, full0 + sj * 8);
        }
    }

    // ---- epilogue: normalize, write bf16 into reordered layout ----
    const int r = lane >> 2, cq = (lane & 3) * 2;
    char* outb = (char*)g_attr;
#pragma unroll
    for (int mi = 0; mi < 2; mi++) {
        float inv0 = 1.f / lrow[2 * mi], inv1 = 1.f / lrow[2 * mi + 1];
        int row0 = bb * SEQ + q0 + wid * 32 + mi * 16 + r;
#pragma unroll
        for (int jh = 0; jh < 8; jh++) {
            int col = h * HDIM + jh * 8 + cq;
            *(uint32_t*)(outb + reord_off(row0, col)) =
                pack_bf16(oa[mi][jh][0] * inv0, oa[mi][jh][1] * inv0);
            *(uint32_t*)(outb + reord_off(row0 + 8, col)) =
                pack_bf16(oa[mi][jh][2] * inv1, oa[mi][jh][3] * inv1);
        }
    }
}

// ======================= residual + LayerNorm ============================
__global__ __launch_bounds__(256)
void ln_kernel(const float* __restrict__ x, const float* __restrict__ gamma,
               const float* __restrict__ beta, float* __restrict__ out)
{
    const int row = blockIdx.x;
    const int t   = threadIdx.x;
    const size_t off = (size_t)row * EMB + t * 4;

    float4 a = *(const float4*)&g_pj[off];
    float4 r = *(const float4*)&x[off];
    float y0 = a.x + r.x, y1 = a.y + r.y, y2 = a.z + r.z, y3 = a.w + r.w;

    float s  = (y0 + y1) + (y2 + y3);
    float ss = fmaf(y0, y0, fmaf(y1, y1, fmaf(y2, y2, y3 * y3)));

#pragma unroll
    for (int offx = 16; offx > 0; offx >>= 1) {
        s  += __shfl_xor_sync(0xffffffffu, s,  offx);
        ss += __shfl_xor_sync(0xffffffffu, ss, offx);
    }
    __shared__ float sbuf[8], ssbuf[8];
    int lane = t & 31, w = t >> 5;
    if (lane == 0) { sbuf[w] = s; ssbuf[w] = ss; }
    __syncthreads();
    if (w == 0) {
        float sv  = (lane < 8) ? sbuf[lane]  : 0.f;
        float ssv = (lane < 8) ? ssbuf[lane] : 0.f;
#pragma unroll
        for (int offx = 4; offx > 0; offx >>= 1) {
            sv  += __shfl_xor_sync(0xffffffffu, sv,  offx);
            ssv += __shfl_xor_sync(0xffffffffu, ssv, offx);
        }
        if (lane == 0) { sbuf[0] = sv; ssbuf[0] = ssv; }
    }
    __syncthreads();
    float mu  = sbuf[0] * (1.f / EMB);
    float var = ssbuf[0] * (1.f / EMB) - mu * mu;
    float rs  = rsqrtf(var + 1e-5f);

    float4 g  = *(const float4*)&gamma[t * 4];
    float4 be = *(const float4*)&beta[t * 4];
    float4 ov;
    ov.x = (y0 - mu) * rs * g.x + be.x;
    ov.y = (y1 - mu) * rs * g.y + be.y;
    ov.z = (y2 - mu) * rs * g.z + be.z;
    ov.w = (y3 - mu) * rs * g.w + be.w;
    *(float4*)&out[off] = ov;
}

// =========================================================================
extern "C" void kernel_launch(void* const* d_in, const int* in_sizes, int n_in,
                              void* d_out, int out_size)
{
    const float* x      = (const float*)d_in[0];
    const float* W_qkv  = (const float*)d_in[1];
    const float* b_qkv  = (const float*)d_in[2];
    const float* W_proj = (const float*)d_in[3];
    const float* b_proj = (const float*)d_in[4];
    const float* gamma  = (const float*)d_in[5];
    const float* beta   = (const float*)d_in[6];
    float* out = (float*)d_out;

    float* pj_buf;  cudaGetSymbolAddress((void**)&pj_buf,  g_pj);
    __nv_bfloat16 *xr, *wqr, *wpr, *attr;
    cudaGetSymbolAddress((void**)&xr,   g_xr);
    cudaGetSymbolAddress((void**)&wqr,  g_wqr);
    cudaGetSymbolAddress((void**)&wpr,  g_wpr);
    cudaGetSymbolAddress((void**)&attr, g_attr);

    cudaFuncSetAttribute(gemm_bulk<1>, cudaFuncAttributeMaxDynamicSharedMemorySize, GEMM_SMEM);
    cudaFuncSetAttribute(gemm_bulk<0>, cudaFuncAttributeMaxDynamicSharedMemorySize, GEMM_SMEM);
    cudaFuncSetAttribute(attn_mma,     cudaFuncAttributeMaxDynamicSharedMemorySize, AT_SMEM);

    // reorder + bf16-convert GEMM inputs
    reord_kernel<<<(MTOT * 128 + 255) / 256, 256>>>(x,      (uint4*)xr,  MTOT * 128);
    reord_kernel<<<(NQKV * 128 + 255) / 256, 256>>>(W_qkv,  (uint4*)wqr, NQKV * 128);
    reord_kernel<<<(EMB  * 128 + 255) / 256, 256>>>(W_proj, (uint4*)wpr, EMB  * 128);

    // 1) QKV projection -> head-major swizzled Q/K/V (Q pre-scaled)
    gemm_bulk<1><<<dim3(NQKV / 128, MTOT / 256), 256, GEMM_SMEM>>>(xr, wqr, b_qkv, nullptr, EMB, NQKV);
    // 2) flash attention -> bf16 attn out (reordered for proj gemm)
    attn_mma<<<dim3(SEQ / 128, HEADS, BATCH), 128, AT_SMEM>>>();
    // 3) output projection -> fp32
    gemm_bulk<0><<<dim3(EMB / 128, MTOT / 256), 256, GEMM_SMEM>>>(attr, wpr, b_proj, pj_buf, EMB, EMB);
    // 4) residual + layernorm
    ln_kernel<<<MTOT, 256>>>(x, gamma, beta, out);
}